// round 7
// baseline (speedup 1.0000x reference)
#include <cuda_runtime.h>
#include <cuda_bf16.h>

#define NH 12
#define DH 64
#define HID 768
#define LSEQ 512
#define BATCH 16
#define NTOK (BATCH*LSEQ)
#define FFND 3072
#define NLAY 6

/* ---------------- scratch ---------------- */
__device__ float g_x [NTOK*HID];
__device__ float g_q [NTOK*HID];
__device__ float g_k [NTOK*HID];
__device__ float g_v [NTOK*HID];
__device__ float g_o [NTOK*HID];
__device__ float g_y [NTOK*HID];
__device__ float g_h [NTOK*FFND];
__device__ float g_fd[BATCH*NH*LSEQ];
__device__ float g_sd[BATCH*NH*LSEQ];
__device__ float g_fg[BATCH*NH*LSEQ];
__device__ float g_sg[BATCH*NH*LSEQ];
__device__ float g_fdm[BATCH*NH*2];
__device__ float g_sdm[BATCH*NH*2];

/* ---------------- block reductions (blockDim=256) ---------------- */
__device__ __forceinline__ float block_sum1(float a, float* red) {
    #pragma unroll
    for (int off = 16; off > 0; off >>= 1) a += __shfl_xor_sync(0xffffffffu, a, off);
    int t = threadIdx.x;
    if ((t & 31) == 0) red[t >> 5] = a;
    __syncthreads();
    if (t == 0) {
        float s = 0.f;
        #pragma unroll
        for (int i = 0; i < 8; i++) s += red[i];
        red[8] = s;
    }
    __syncthreads();
    return red[8];
}

__device__ __forceinline__ void block_sum2(float& a, float& b, float* red) {
    #pragma unroll
    for (int off = 16; off > 0; off >>= 1) {
        a += __shfl_xor_sync(0xffffffffu, a, off);
        b += __shfl_xor_sync(0xffffffffu, b, off);
    }
    int t = threadIdx.x;
    if ((t & 31) == 0) { red[t >> 5] = a; red[8 + (t >> 5)] = b; }
    __syncthreads();
    if (t == 0) {
        float sa = 0.f, sb = 0.f;
        #pragma unroll
        for (int i = 0; i < 8; i++) { sa += red[i]; sb += red[8 + i]; }
        red[16] = sa; red[17] = sb;
    }
    __syncthreads();
    a = red[16]; b = red[17];
}

/* ---------------- embedding + LN ---------------- */
__global__ __launch_bounds__(256) void embed_kernel(
    const int* __restrict__ ids, const float* __restrict__ we,
    const float* __restrict__ te, const float* __restrict__ pe,
    const float* __restrict__ lw, const float* __restrict__ lb,
    float* __restrict__ x)
{
    __shared__ float buf[HID];
    __shared__ float red[32];
    int row = blockIdx.x, t = threadIdx.x;
    int l = row & (LSEQ - 1);
    int id = ids[row];
    float s = 0.f;
    for (int j = t; j < HID; j += 256) {
        float v = we[(size_t)id * HID + j] + te[j] + pe[(size_t)l * HID + j];
        buf[j] = v; s += v;
    }
    float mean = block_sum1(s, red) * (1.f / HID);
    float vs = 0.f;
    for (int j = t; j < HID; j += 256) { float d = buf[j] - mean; vs += d * d; }
    float var = block_sum1(vs, red) * (1.f / HID);
    float inv = 1.0f / sqrtf(var + 1e-12f);
    for (int j = t; j < HID; j += 256)
        x[(size_t)row * HID + j] = (buf[j] - mean) * inv * lw[j] + lb[j];
}

/* ---------------- residual + optional bias + LN ---------------- */
__global__ __launch_bounds__(256) void ln_res_kernel(
    const float* __restrict__ resid, const float* __restrict__ y,
    const float* __restrict__ bias, const float* __restrict__ w,
    const float* __restrict__ bp, float* __restrict__ out)
{
    __shared__ float buf[HID];
    __shared__ float red[32];
    int row = blockIdx.x, t = threadIdx.x;
    float s = 0.f;
    for (int j = t; j < HID; j += 256) {
        float v = resid[(size_t)row * HID + j] + y[(size_t)row * HID + j];
        if (bias) v += bias[j];
        buf[j] = v; s += v;
    }
    float mean = block_sum1(s, red) * (1.f / HID);
    float vs = 0.f;
    for (int j = t; j < HID; j += 256) { float d = buf[j] - mean; vs += d * d; }
    float var = block_sum1(vs, red) * (1.f / HID);
    float inv = 1.0f / sqrtf(var + 1e-12f);
    for (int j = t; j < HID; j += 256)
        out[(size_t)row * HID + j] = (buf[j] - mean) * inv * w[j] + bp[j];
}

/* ---------------- 128x128 SGEMM; epi: 0 plain, 1 silu+scatter, 2 bias+gelu ---------------- */
__global__ __launch_bounds__(256) void sgemm128(
    const float* __restrict__ A, const float* __restrict__ B, float* __restrict__ C,
    int K, int N, int epi, const float* __restrict__ bias)
{
    __shared__ float As[16][128];
    __shared__ float Bs[16][128];
    int t = threadIdx.x;
    int bx = blockIdx.x, by = blockIdx.y;
    int tx = t & 15, ty = t >> 4;
    const float* Ab = A + (size_t)(by * 128) * K;
    const float* Bb = B + bx * 128;
    float acc[8][8];
    #pragma unroll
    for (int i = 0; i < 8; i++)
        #pragma unroll
        for (int j = 0; j < 8; j++) acc[i][j] = 0.f;

    for (int kt = 0; kt < K; kt += 16) {
        #pragma unroll
        for (int u = 0; u < 2; u++) {
            int idx = u * 256 + t;
            int ar = idx >> 2, aq = idx & 3;
            float4 av = *(const float4*)(Ab + (size_t)ar * K + kt + aq * 4);
            As[aq * 4 + 0][ar] = av.x; As[aq * 4 + 1][ar] = av.y;
            As[aq * 4 + 2][ar] = av.z; As[aq * 4 + 3][ar] = av.w;
        }
        #pragma unroll
        for (int u = 0; u < 2; u++) {
            int idx = u * 256 + t;
            int bk = idx >> 5, bq = idx & 31;
            *(float4*)(&Bs[bk][bq * 4]) = *(const float4*)(Bb + (size_t)(kt + bk) * N + bq * 4);
        }
        __syncthreads();
        #pragma unroll
        for (int kk = 0; kk < 16; kk++) {
            float a[8], b[8];
            #pragma unroll
            for (int i = 0; i < 8; i++) a[i] = As[kk][ty * 8 + i];
            #pragma unroll
            for (int j = 0; j < 8; j++) b[j] = Bs[kk][tx * 8 + j];
            #pragma unroll
            for (int i = 0; i < 8; i++)
                #pragma unroll
                for (int j = 0; j < 8; j++) acc[i][j] += a[i] * b[j];
        }
        __syncthreads();
    }

    #pragma unroll
    for (int i = 0; i < 8; i++) {
        int row = by * 128 + ty * 8 + i;
        #pragma unroll
        for (int j = 0; j < 8; j++) {
            int col = bx * 128 + tx * 8 + j;
            float v = acc[i][j];
            if (epi == 1) {
                float sv = v / (1.0f + expf(-v));
                int b_ = row >> 9, l = row & (LSEQ - 1), h = col >> 6, d = col & 63;
                C[(size_t)((b_ * NH + h) * LSEQ + l) * DH + d] = sv;
            } else if (epi == 2) {
                float vv = v + bias[col];
                C[(size_t)row * N + col] = 0.5f * vv * (1.0f + erff(vv * 0.70710678118654752f));
            } else {
                C[(size_t)row * N + col] = v;
            }
        }
    }
}

/* ---------------- gates: 4x [8192,768]@[768,12] + sigmoid -> [b,h,l] ---------------- */
__global__ __launch_bounds__(256) void gates_kernel(
    const float* __restrict__ x,
    const float* __restrict__ fdw, const float* __restrict__ sdw,
    const float* __restrict__ fgw, const float* __restrict__ sgw,
    const float* __restrict__ fdb, const float* __restrict__ sdb,
    float* __restrict__ fd, float* __restrict__ sd,
    float* __restrict__ fg, float* __restrict__ sg)
{
    __shared__ float xs[64][68];
    __shared__ float ws[64][48];
    int t = threadIdx.x;
    int blk = blockIdx.x;
    int r = t >> 2, g = t & 3;
    float acc[12];
    #pragma unroll
    for (int j = 0; j < 12; j++) acc[j] = 0.f;

    for (int kt = 0; kt < HID; kt += 64) {
        #pragma unroll
        for (int u = 0; u < 4; u++) {
            int idx = u * 256 + t;
            int xr = idx >> 4, xq = idx & 15;
            float4 xv = *(const float4*)(x + (size_t)(blk * 64 + xr) * HID + kt + xq * 4);
            xs[xr][xq * 4 + 0] = xv.x; xs[xr][xq * 4 + 1] = xv.y;
            xs[xr][xq * 4 + 2] = xv.z; xs[xr][xq * 4 + 3] = xv.w;
        }
        #pragma unroll
        for (int u = 0; u < 12; u++) {
            int idx = u * 256 + t;
            int wk = idx / 48, wj = idx % 48;
            int m = wj / 12, jj = wj % 12;
            const float* W = (m == 0) ? fdw : (m == 1) ? sdw : (m == 2) ? fgw : sgw;
            ws[wk][wj] = W[(size_t)(kt + wk) * NH + jj];
        }
        __syncthreads();
        for (int kk = 0; kk < 64; kk++) {
            float xv = xs[r][kk];
            #pragma unroll
            for (int j = 0; j < 12; j++) acc[j] += xv * ws[kk][g * 12 + j];
        }
        __syncthreads();
    }
    int token = blk * 64 + r;
    int b = token >> 9, l = token & (LSEQ - 1);
    float* dst = (g == 0) ? fd : (g == 1) ? sd : (g == 2) ? fg : sg;
    #pragma unroll
    for (int j = 0; j < 12; j++) {
        float vv = acc[j];
        if (g == 0) vv += fdb[j];
        else if (g == 1) vv += sdb[j];
        vv = 1.0f / (1.0f + expf(-vv));
        dst[(size_t)(b * NH + j) * LSEQ + l] = vv;
    }
}

/* ---------------- chunk means of fd/sd ---------------- */
__global__ __launch_bounds__(256) void cmean_kernel(
    const float* __restrict__ fd, const float* __restrict__ sd,
    float* __restrict__ fdm, float* __restrict__ sdm)
{
    __shared__ float red[32];
    int bid = blockIdx.x;              /* bh*2 + chunk */
    int bh = bid >> 1, c = bid & 1;
    int t = threadIdx.x;
    float a = fd[(size_t)bh * LSEQ + c * 256 + t];
    float b = sd[(size_t)bh * LSEQ + c * 256 + t];
    block_sum2(a, b, red);
    if (t == 0) { fdm[bid] = a * (1.f / 256.f); sdm[bid] = b * (1.f / 256.f); }
}

/* ---------------- delta rule: one 256-thread CTA per (b,h) ----------------
   per chunk: decay, rf=1/(fro+eps); G=k^T k, A=k^T v;
   o = a*fg*(q@Sf)*rf + (1-a)*sg*(q@Ss)*rs;
   Sf = Sf + A - (G@Sf)*rf  (then fro-normalize); same for Ss.            */
#define SPAD 257
#define QPAD 66
#define DELTA_SMEM_BYTES ((4*4096 + 2*16896 + 40) * 4)

__global__ __launch_bounds__(256, 1) void delta_kernel(
    const float* __restrict__ q, const float* __restrict__ k, const float* __restrict__ v,
    const float* __restrict__ fg, const float* __restrict__ sg,
    const float* __restrict__ fdm, const float* __restrict__ sdm,
    float* __restrict__ o)
{
    extern __shared__ float sm[];
    float* Sf = sm;
    float* Ss = Sf + 4096;
    float* G  = Ss + 4096;
    float* A  = G + 4096;
    float* T0 = A + 4096;       /* kT (padded 257) then q (padded 66) */
    float* T1 = T0 + 16896;     /* vT (padded 257) */
    float* red = T1 + 16896;

    int t = threadIdx.x;
    int bh = blockIdx.x;
    int b = bh / NH, h = bh % NH;
    int d = t >> 2, g = t & 3, e0 = g * 16;

    #pragma unroll
    for (int j = 0; j < 16; j++) { Sf[d * 64 + e0 + j] = 0.f; Ss[d * 64 + e0 + j] = 0.f; }
    __syncthreads();

    const float* qb = q + (size_t)bh * LSEQ * DH;
    const float* kb = k + (size_t)bh * LSEQ * DH;
    const float* vb = v + (size_t)bh * LSEQ * DH;

    for (int c = 0; c < 2; c++) {
        int c0 = c * 256;
        float df = powf(fdm[bh * 2 + c], 256.0f);
        float ds = powf(sdm[bh * 2 + c], 256.0f);

        /* decay + Frobenius of decayed state */
        float pf = 0.f, ps = 0.f;
        #pragma unroll
        for (int j = 0; j < 16; j++) {
            int idx = d * 64 + e0 + j;
            float a = Sf[idx] * df; Sf[idx] = a; pf += a * a;
            float bb = Ss[idx] * ds; Ss[idx] = bb; ps += bb * bb;
        }
        block_sum2(pf, ps, red);
        float rf = 1.0f / (sqrtf(pf) + 1e-8f);
        float rs = 1.0f / (sqrtf(ps) + 1e-8f);

        /* stage kT, vT (transposed, pad 257) */
        #pragma unroll
        for (int u = 0; u < 16; u++) {
            int idx4 = u * 256 + t;
            int r = idx4 >> 4, e4 = (idx4 & 15) * 4;
            float4 kv = *(const float4*)(kb + (size_t)(c0 + r) * DH + e4);
            T0[(e4 + 0) * SPAD + r] = kv.x; T0[(e4 + 1) * SPAD + r] = kv.y;
            T0[(e4 + 2) * SPAD + r] = kv.z; T0[(e4 + 3) * SPAD + r] = kv.w;
            float4 vv = *(const float4*)(vb + (size_t)(c0 + r) * DH + e4);
            T1[(e4 + 0) * SPAD + r] = vv.x; T1[(e4 + 1) * SPAD + r] = vv.y;
            T1[(e4 + 2) * SPAD + r] = vv.z; T1[(e4 + 3) * SPAD + r] = vv.w;
        }
        __syncthreads();

        /* G = k^T k, A = k^T v */
        {
            float accG[16], accA[16];
            #pragma unroll
            for (int j = 0; j < 16; j++) { accG[j] = 0.f; accA[j] = 0.f; }
            for (int r = 0; r < 256; r++) {
                float kd = T0[d * SPAD + r];
                #pragma unroll
                for (int j = 0; j < 16; j++) {
                    accG[j] += kd * T0[(e0 + j) * SPAD + r];
                    accA[j] += kd * T1[(e0 + j) * SPAD + r];
                }
            }
            #pragma unroll
            for (int j = 0; j < 16; j++) { G[d * 64 + e0 + j] = accG[j]; A[d * 64 + e0 + j] = accA[j]; }
        }
        __syncthreads();

        /* stage q row-major (pad 66) into T0 */
        #pragma unroll
        for (int u = 0; u < 16; u++) {
            int idx4 = u * 256 + t;
            int r = idx4 >> 4, e4 = (idx4 & 15) * 4;
            float4 qv = *(const float4*)(qb + (size_t)(c0 + r) * DH + e4);
            T0[r * QPAD + e4 + 0] = qv.x; T0[r * QPAD + e4 + 1] = qv.y;
            T0[r * QPAD + e4 + 2] = qv.z; T0[r * QPAD + e4 + 3] = qv.w;
        }
        __syncthreads();

        /* outputs: row r=d handled by 4 threads, 16 cols each */
        {
            float of[16], os[16];
            #pragma unroll
            for (int j = 0; j < 16; j++) { of[j] = 0.f; os[j] = 0.f; }
            for (int kk = 0; kk < 64; kk++) {
                float qv = T0[d * QPAD + kk];
                #pragma unroll
                for (int j = 0; j < 16; j++) {
                    of[j] += qv * Sf[kk * 64 + e0 + j];
                    os[j] += qv * Ss[kk * 64 + e0 + j];
                }
            }
            float fgv = fg[(size_t)bh * LSEQ + c0 + d];
            float sgv = sg[(size_t)bh * LSEQ + c0 + d];
            float* orow = o + (size_t)(b * LSEQ + c0 + d) * HID + h * DH + e0;
            #pragma unroll
            for (int j = 0; j < 16; j++)
                orow[j] = 0.6f * fgv * of[j] * rf + 0.4f * sgv * os[j] * rs;
        }

        /* Tf = G@Sf, Ts = G@Ss; update + normalize */
        {
            float tf[16], ts[16];
            #pragma unroll
            for (int j = 0; j < 16; j++) { tf[j] = 0.f; ts[j] = 0.f; }
            for (int kk = 0; kk < 64; kk++) {
                float gv = G[d * 64 + kk];
                #pragma unroll
                for (int j = 0; j < 16; j++) {
                    tf[j] += gv * Sf[kk * 64 + e0 + j];
                    ts[j] += gv * Ss[kk * 64 + e0 + j];
                }
            }
            __syncthreads();
            float nf = 0.f, ns = 0.f;
            #pragma unroll
            for (int j = 0; j < 16; j++) {
                int idx = d * 64 + e0 + j;
                float sv = Sf[idx] + A[idx] - tf[j] * rf;
                Sf[idx] = sv; nf += sv * sv;
                float sw = Ss[idx] + A[idx] - ts[j] * rs;
                Ss[idx] = sw; ns += sw * sw;
            }
            block_sum2(nf, ns, red);
            float qf = 1.0f / (sqrtf(nf) + 1e-8f);
            float qs = 1.0f / (sqrtf(ns) + 1e-8f);
            #pragma unroll
            for (int j = 0; j < 16; j++) {
                int idx = d * 64 + e0 + j;
                Sf[idx] *= qf; Ss[idx] *= qs;
            }
            __syncthreads();
        }
    }
}

/* ---------------- per-(b,l,h) rms norm over d=64, in place ---------------- */
__global__ __launch_bounds__(256) void rms_kernel(float* __restrict__ o, const float* __restrict__ w)
{
    int warp = threadIdx.x >> 5, lane = threadIdx.x & 31;
    size_t row = (size_t)blockIdx.x * 8 + warp;
    float2* p = (float2*)(o + row * DH) + lane;
    float2 v = *p;
    float ss = v.x * v.x + v.y * v.y;
    #pragma unroll
    for (int off = 16; off > 0; off >>= 1) ss += __shfl_xor_sync(0xffffffffu, ss, off);
    float inv = 1.0f / sqrtf(ss * (1.f / 64.f) + 1e-6f);
    v.x = v.x * inv * w[lane * 2];
    v.y = v.y * inv * w[lane * 2 + 1];
    *p = v;
}

/* ---------------- host ---------------- */
static float* symf(const void* sym) { void* p = nullptr; cudaGetSymbolAddress(&p, sym); return (float*)p; }

extern "C" void kernel_launch(void* const* d_in, const int* in_sizes, int n_in,
                              void* d_out, int out_size)
{
    const int*   ids = (const int*)  d_in[0];
    const float* we  = (const float*)d_in[1];
    const float* te  = (const float*)d_in[2];
    const float* pe  = (const float*)d_in[3];
    const float* elw = (const float*)d_in[4];
    const float* elb = (const float*)d_in[5];
    const float* qw  = (const float*)d_in[6];
    const float* kw  = (const float*)d_in[7];
    const float* vw  = (const float*)d_in[8];
    const float* fdw = (const float*)d_in[9];
    const float* fdb = (const float*)d_in[10];
    const float* sdw = (const float*)d_in[11];
    const float* sdb = (const float*)d_in[12];
    const float* fgw = (const float*)d_in[13];
    const float* sgw = (const float*)d_in[14];
    const float* onw = (const float*)d_in[15];
    const float* ow  = (const float*)d_in[16];
    const float* alw = (const float*)d_in[17];
    const float* alb = (const float*)d_in[18];
    const float* w1  = (const float*)d_in[19];
    const float* b1  = (const float*)d_in[20];
    const float* w2  = (const float*)d_in[21];
    const float* b2  = (const float*)d_in[22];
    const float* flw = (const float*)d_in[23];
    const float* flb = (const float*)d_in[24];
    float* out = (float*)d_out;

    float* px  = symf(g_x);  float* pq  = symf(g_q);  float* pk  = symf(g_k);
    float* pv  = symf(g_v);  float* po  = symf(g_o);  float* py  = symf(g_y);
    float* ph  = symf(g_h);
    float* pfd = symf(g_fd); float* psd = symf(g_sd);
    float* pfg = symf(g_fg); float* psg = symf(g_sg);
    float* pfdm = symf(g_fdm); float* psdm = symf(g_sdm);

    static bool attr_done = false;
    if (!attr_done) {
        cudaFuncSetAttribute(delta_kernel, cudaFuncAttributeMaxDynamicSharedMemorySize, DELTA_SMEM_BYTES);
        attr_done = true;
    }

    embed_kernel<<<NTOK, 256>>>(ids, we, te, pe, elw, elb, px);

    for (int i = 0; i < NLAY; i++) {
        const float* qwi = qw + (size_t)i * HID * HID;
        const float* kwi = kw + (size_t)i * HID * HID;
        const float* vwi = vw + (size_t)i * HID * HID;
        const float* owi = ow + (size_t)i * HID * HID;

        dim3 gQ(HID / 128, NTOK / 128);
        sgemm128<<<gQ, 256>>>(px, qwi, pq, HID, HID, 1, nullptr);
        sgemm128<<<gQ, 256>>>(px, kwi, pk, HID, HID, 1, nullptr);
        sgemm128<<<gQ, 256>>>(px, vwi, pv, HID, HID, 1, nullptr);

        gates_kernel<<<NTOK / 64, 256>>>(px,
            fdw + (size_t)i * HID * NH, sdw + (size_t)i * HID * NH,
            fgw + (size_t)i * HID * NH, sgw + (size_t)i * HID * NH,
            fdb + (size_t)i * NH, sdb + (size_t)i * NH,
            pfd, psd, pfg, psg);

        cmean_kernel<<<BATCH * NH * 2, 256>>>(pfd, psd, pfdm, psdm);

        delta_kernel<<<BATCH * NH, 256, DELTA_SMEM_BYTES>>>(pq, pk, pv, pfg, psg, pfdm, psdm, po);

        rms_kernel<<<(NTOK * NH) / 8, 256>>>(po, onw + (size_t)i * DH);

        sgemm128<<<gQ, 256>>>(po, owi, py, HID, HID, 0, nullptr);
        ln_res_kernel<<<NTOK, 256>>>(px, py, nullptr,
            alw + (size_t)i * HID, alb + (size_t)i * HID, px);

        dim3 gF1(FFND / 128, NTOK / 128);
        sgemm128<<<gF1, 256>>>(px, w1 + (size_t)i * HID * FFND, ph, HID, FFND, 2, b1 + (size_t)i * FFND);

        dim3 gF2(HID / 128, NTOK / 128);
        sgemm128<<<gF2, 256>>>(ph, w2 + (size_t)i * FFND * HID, py, FFND, HID, 0, nullptr);

        float* dst = (i == NLAY - 1) ? out : px;
        ln_res_kernel<<<NTOK, 256>>>(px, py, b2 + (size_t)i * HID,
            flw + (size_t)i * HID, flb + (size_t)i * HID, dst);
    }
}

// round 9
// speedup vs baseline: 2.0510x; 2.0510x over previous
#include <cuda_runtime.h>
#include <cuda_bf16.h>
#include <cstdint>

#define NH 12
#define DH 64
#define HID 768
#define LSEQ 512
#define BATCH 16
#define NTOK (BATCH*LSEQ)
#define FFND 3072
#define NLAY 6

#define WQKV (HID*HID)            /* 589824  */
#define WFFN (HID*FFND)           /* 2359296 */
#define WLAYER (4*WQKV + 2*WFFN)  /* 7077888 */

/* ---------------- scratch ---------------- */
__device__ float g_x [NTOK*HID];
__device__ float g_q [NTOK*HID];
__device__ float g_k [NTOK*HID];
__device__ float g_v [NTOK*HID];
__device__ float g_o [NTOK*HID];
__device__ float g_y [NTOK*HID];
__device__ float g_h [NTOK*FFND];
__device__ float g_fd[BATCH*NH*LSEQ];
__device__ float g_sd[BATCH*NH*LSEQ];
__device__ float g_fg[BATCH*NH*LSEQ];
__device__ float g_sg[BATCH*NH*LSEQ];
__device__ float g_fdm[BATCH*NH*2];
__device__ float g_sdm[BATCH*NH*2];
__device__ __align__(16) __nv_bfloat16 g_wth[NLAY*WLAYER];
__device__ __align__(16) __nv_bfloat16 g_wtl[NLAY*WLAYER];
__device__ __align__(16) __nv_bfloat16 g_ah[NTOK*FFND];
__device__ __align__(16) __nv_bfloat16 g_al[NTOK*FFND];

/* ---------------- PTX helpers (no arch-suffix instructions) ---------------- */
__device__ __forceinline__ uint32_t smem_u32(const void* p) {
    uint32_t a;
    asm("{ .reg .u64 t; cvta.to.shared.u64 t, %1; cvt.u32.u64 %0, t; }" : "=r"(a) : "l"(p));
    return a;
}
__device__ __forceinline__ void cp_async16(uint32_t saddr, const void* gaddr) {
    asm volatile("cp.async.cg.shared.global [%0], [%1], 16;" :: "r"(saddr), "l"(gaddr) : "memory");
}
__device__ __forceinline__ void cp_commit() {
    asm volatile("cp.async.commit_group;" ::: "memory");
}
template <int N>
__device__ __forceinline__ void cp_wait() {
    asm volatile("cp.async.wait_group %0;" :: "n"(N) : "memory");
}
__device__ __forceinline__ void ldsm_x4(uint32_t* r, uint32_t a) {
    asm volatile("ldmatrix.sync.aligned.m8n8.x4.shared.b16 {%0,%1,%2,%3}, [%4];"
        : "=r"(r[0]), "=r"(r[1]), "=r"(r[2]), "=r"(r[3]) : "r"(a));
}
__device__ __forceinline__ void ldsm_x2(uint32_t* r, uint32_t a) {
    asm volatile("ldmatrix.sync.aligned.m8n8.x2.shared.b16 {%0,%1}, [%2];"
        : "=r"(r[0]), "=r"(r[1]) : "r"(a));
}
__device__ __forceinline__ void mma16816(float* d, const uint32_t* a, const uint32_t* b) {
    asm volatile("mma.sync.aligned.m16n8k16.row.col.f32.bf16.bf16.f32 "
        "{%0,%1,%2,%3}, {%4,%5,%6,%7}, {%8,%9}, {%0,%1,%2,%3};"
        : "+f"(d[0]), "+f"(d[1]), "+f"(d[2]), "+f"(d[3])
        : "r"(a[0]), "r"(a[1]), "r"(a[2]), "r"(a[3]), "r"(b[0]), "r"(b[1]));
}

/* ---------------- block reductions (blockDim=256) ---------------- */
__device__ __forceinline__ float block_sum1(float a, float* red) {
    #pragma unroll
    for (int off = 16; off > 0; off >>= 1) a += __shfl_xor_sync(0xffffffffu, a, off);
    int t = threadIdx.x;
    if ((t & 31) == 0) red[t >> 5] = a;
    __syncthreads();
    if (t == 0) {
        float s = 0.f;
        #pragma unroll
        for (int i = 0; i < 8; i++) s += red[i];
        red[8] = s;
    }
    __syncthreads();
    return red[8];
}

__device__ __forceinline__ void block_sum2(float& a, float& b, float* red) {
    #pragma unroll
    for (int off = 16; off > 0; off >>= 1) {
        a += __shfl_xor_sync(0xffffffffu, a, off);
        b += __shfl_xor_sync(0xffffffffu, b, off);
    }
    int t = threadIdx.x;
    if ((t & 31) == 0) { red[t >> 5] = a; red[8 + (t >> 5)] = b; }
    __syncthreads();
    if (t == 0) {
        float sa = 0.f, sb = 0.f;
        #pragma unroll
        for (int i = 0; i < 8; i++) { sa += red[i]; sb += red[8 + i]; }
        red[16] = sa; red[17] = sb;
    }
    __syncthreads();
    a = red[16]; b = red[17];
}

/* ---------------- embedding + LN ---------------- */
__global__ __launch_bounds__(256) void embed_kernel(
    const int* __restrict__ ids, const float* __restrict__ we,
    const float* __restrict__ te, const float* __restrict__ pe,
    const float* __restrict__ lw, const float* __restrict__ lb,
    float* __restrict__ x)
{
    __shared__ float buf[HID];
    __shared__ float red[32];
    int row = blockIdx.x, t = threadIdx.x;
    int l = row & (LSEQ - 1);
    int id = ids[row];
    float s = 0.f;
    for (int j = t; j < HID; j += 256) {
        float v = we[(size_t)id * HID + j] + te[j] + pe[(size_t)l * HID + j];
        buf[j] = v; s += v;
    }
    float mean = block_sum1(s, red) * (1.f / HID);
    float vs = 0.f;
    for (int j = t; j < HID; j += 256) { float d = buf[j] - mean; vs += d * d; }
    float var = block_sum1(vs, red) * (1.f / HID);
    float inv = 1.0f / sqrtf(var + 1e-12f);
    for (int j = t; j < HID; j += 256)
        x[(size_t)row * HID + j] = (buf[j] - mean) * inv * lw[j] + lb[j];
}

/* ---------------- residual + optional bias + LN ---------------- */
__global__ __launch_bounds__(256) void ln_res_kernel(
    const float* __restrict__ resid, const float* __restrict__ y,
    const float* __restrict__ bias, const float* __restrict__ w,
    const float* __restrict__ bp, float* __restrict__ out)
{
    __shared__ float buf[HID];
    __shared__ float red[32];
    int row = blockIdx.x, t = threadIdx.x;
    float s = 0.f;
    for (int j = t; j < HID; j += 256) {
        float v = resid[(size_t)row * HID + j] + y[(size_t)row * HID + j];
        if (bias) v += bias[j];
        buf[j] = v; s += v;
    }
    float mean = block_sum1(s, red) * (1.f / HID);
    float vs = 0.f;
    for (int j = t; j < HID; j += 256) { float d = buf[j] - mean; vs += d * d; }
    float var = block_sum1(vs, red) * (1.f / HID);
    float inv = 1.0f / sqrtf(var + 1e-12f);
    for (int j = t; j < HID; j += 256)
        out[(size_t)row * HID + j] = (buf[j] - mean) * inv * w[j] + bp[j];
}

/* ---------------- fp32 -> bf16 hi/lo split (4 elems/thread) ---------------- */
__global__ __launch_bounds__(256) void split_kernel(
    const float4* __restrict__ x, __nv_bfloat162* __restrict__ h, __nv_bfloat162* __restrict__ l)
{
    size_t i = (size_t)blockIdx.x * 256 + threadIdx.x;
    float4 v = x[i];
    __nv_bfloat16 h0 = __float2bfloat16(v.x);
    __nv_bfloat16 h1 = __float2bfloat16(v.y);
    __nv_bfloat16 h2 = __float2bfloat16(v.z);
    __nv_bfloat16 h3 = __float2bfloat16(v.w);
    h[2*i]   = __nv_bfloat162(h0, h1);
    h[2*i+1] = __nv_bfloat162(h2, h3);
    l[2*i]   = __nv_bfloat162(__float2bfloat16(v.x - __bfloat162float(h0)),
                              __float2bfloat16(v.y - __bfloat162float(h1)));
    l[2*i+1] = __nv_bfloat162(__float2bfloat16(v.z - __bfloat162float(h2)),
                              __float2bfloat16(v.w - __bfloat162float(h3)));
}

/* ---------------- weight transpose + split: W[K,N] -> Th,Tl[N,K] bf16 ---------------- */
__global__ void tsplit_kernel(const float* __restrict__ W,
                              __nv_bfloat16* __restrict__ Th, __nv_bfloat16* __restrict__ Tl,
                              int K, int N)
{
    __shared__ float tile[32][33];
    int k0 = blockIdx.y * 32, n0 = blockIdx.x * 32;
    int tx = threadIdx.x, ty = threadIdx.y;
    #pragma unroll
    for (int j = 0; j < 4; j++)
        tile[ty + 8*j][tx] = W[(size_t)(k0 + ty + 8*j) * N + n0 + tx];
    __syncthreads();
    #pragma unroll
    for (int j = 0; j < 4; j++) {
        int n = n0 + ty + 8*j, k = k0 + tx;
        float v = tile[tx][ty + 8*j];
        __nv_bfloat16 hv = __float2bfloat16(v);
        Th[(size_t)n * K + k] = hv;
        Tl[(size_t)n * K + k] = __float2bfloat16(v - __bfloat162float(hv));
    }
}

/* ---------------- bf16x3 warp-MMA GEMM: C[M,N] = A[M,K] @ Bt[N,K]^T ----------------
   A,B as bf16 hi/lo; fp32 acc over Ah@Bh + Ah@Bl + Al@Bh.
   128x128 tile, BK=32, cp.async double buffer, 8 warps x (64x32).
   epi: 0 plain, 1 silu+scatter[b,h,l,d], 2 bias+gelu. */
#define BK 32
#define LDS 40                    /* bf16 row stride in smem (80B) */
#define ARR_ELEM (128*LDS)        /* 5120 bf16 per array */
#define STAGE_ELEM (4*ARR_ELEM)   /* 20480 bf16 per stage */
#define GEMM_SMEM (2*STAGE_ELEM*2)/* 81920 bytes */

__global__ __launch_bounds__(256) void gemm_bf3(
    const __nv_bfloat16* __restrict__ Ah, const __nv_bfloat16* __restrict__ Al,
    const __nv_bfloat16* __restrict__ Bh, const __nv_bfloat16* __restrict__ Bl,
    float* __restrict__ C, int K, int N, int epi, const float* __restrict__ bias)
{
    extern __shared__ __nv_bfloat16 smem[];
    uint32_t smb = smem_u32(smem);
    int tid = threadIdx.x, lane = tid & 31, wid = tid >> 5;
    int bx = blockIdx.x, by = blockIdx.y;
    int wy = wid >> 2, wx = wid & 3;
    int m0 = wy * 64, n0 = wx * 32;

    /* global srcs (bytes) */
    const char* gsrc[4] = {
        (const char*)(Ah + (size_t)(by * 128) * K),
        (const char*)(Al + (size_t)(by * 128) * K),
        (const char*)(Bh + (size_t)(bx * 128) * K),
        (const char*)(Bl + (size_t)(bx * 128) * K)
    };

    /* per-thread cp.async coords: i in {tid, tid+256} of 512 uint4 slots per array */
    int r0 = tid >> 2, c0q = tid & 3;           /* slot tid   */
    int r1 = (tid + 256) >> 2, c1q = tid & 3;   /* slot tid+256 (c same since +256 ≡ 0 mod 4) */

    float acc[4][4][4];
    #pragma unroll
    for (int mt = 0; mt < 4; mt++)
        #pragma unroll
        for (int nt = 0; nt < 4; nt++)
            #pragma unroll
            for (int e = 0; e < 4; e++) acc[mt][nt][e] = 0.f;

    int NKB = K / BK;

    /* prefetch slab 0 into stage 0 */
    {
        #pragma unroll
        for (int m = 0; m < 4; m++) {
            uint32_t sb = smb + (uint32_t)(m * ARR_ELEM) * 2;
            cp_async16(sb + (uint32_t)(r0 * LDS + c0q * 8) * 2, gsrc[m] + (size_t)r0 * K * 2 + c0q * 16);
            cp_async16(sb + (uint32_t)(r1 * LDS + c1q * 8) * 2, gsrc[m] + (size_t)r1 * K * 2 + c1q * 16);
        }
        cp_commit();
    }

    /* ldmatrix lane addressing */
    int aj = lane >> 3;
    int arow = ((aj & 1) << 3) + (lane & 7);
    int acol = (aj >> 1) << 3;
    int l16 = lane & 15;
    int brow = l16 & 7;
    int bcol = (l16 >> 3) << 3;

    for (int kb = 0; kb < NKB; kb++) {
        int s = kb & 1;
        if (kb + 1 < NKB) {
            int s2 = s ^ 1;
            int koff = (kb + 1) * (BK * 2);   /* byte offset in K */
            #pragma unroll
            for (int m = 0; m < 4; m++) {
                uint32_t sb = smb + (uint32_t)(s2 * STAGE_ELEM + m * ARR_ELEM) * 2;
                cp_async16(sb + (uint32_t)(r0 * LDS + c0q * 8) * 2, gsrc[m] + (size_t)r0 * K * 2 + koff + c0q * 16);
                cp_async16(sb + (uint32_t)(r1 * LDS + c1q * 8) * 2, gsrc[m] + (size_t)r1 * K * 2 + koff + c1q * 16);
            }
            cp_commit();
            cp_wait<1>();
        } else {
            cp_wait<0>();
        }
        __syncthreads();

        uint32_t stb = smb + (uint32_t)(s * STAGE_ELEM) * 2;
        uint32_t aAh = stb;
        uint32_t aAl = stb + (uint32_t)ARR_ELEM * 2;
        uint32_t aBh = stb + (uint32_t)(2 * ARR_ELEM) * 2;
        uint32_t aBl = stb + (uint32_t)(3 * ARR_ELEM) * 2;

        #pragma unroll
        for (int ks = 0; ks < 2; ks++) {
            int kc = ks * 16;
            uint32_t ah[4][4], al[4][4];
            #pragma unroll
            for (int mt = 0; mt < 4; mt++) {
                uint32_t off = (uint32_t)((m0 + mt * 16 + arow) * LDS + kc + acol) * 2;
                ldsm_x4(ah[mt], aAh + off);
                ldsm_x4(al[mt], aAl + off);
            }
            #pragma unroll
            for (int nt = 0; nt < 4; nt++) {
                uint32_t boff = (uint32_t)((n0 + nt * 8 + brow) * LDS + kc + bcol) * 2;
                uint32_t bh[2], bl[2];
                ldsm_x2(bh, aBh + boff);
                ldsm_x2(bl, aBl + boff);
                #pragma unroll
                for (int mt = 0; mt < 4; mt++) {
                    mma16816(acc[mt][nt], ah[mt], bh);
                    mma16816(acc[mt][nt], ah[mt], bl);
                    mma16816(acc[mt][nt], al[mt], bh);
                }
            }
        }
        __syncthreads();
    }

    /* epilogue */
    int gm0 = by * 128 + m0;
    int gn0 = bx * 128 + n0;
    #pragma unroll
    for (int mt = 0; mt < 4; mt++) {
        #pragma unroll
        for (int nt = 0; nt < 4; nt++) {
            int row0 = gm0 + mt * 16 + (lane >> 2);
            int col0 = gn0 + nt * 8 + (lane & 3) * 2;
            #pragma unroll
            for (int e = 0; e < 4; e++) {
                int row = row0 + ((e >> 1) << 3);
                int col = col0 + (e & 1);
                float v = acc[mt][nt][e];
                if (epi == 1) {
                    float sv = v / (1.0f + expf(-v));
                    int b_ = row >> 9, l = row & (LSEQ - 1);
                    int h = col >> 6, d = col & 63;
                    C[(size_t)((b_ * NH + h) * LSEQ + l) * DH + d] = sv;
                } else if (epi == 2) {
                    float vv = v + bias[col];
                    C[(size_t)row * N + col] = 0.5f * vv * (1.0f + erff(vv * 0.70710678118654752f));
                } else {
                    C[(size_t)row * N + col] = v;
                }
            }
        }
    }
}

/* ---------------- gates: 4x [8192,768]@[768,12] + sigmoid -> [b,h,l] ---------------- */
__global__ __launch_bounds__(256) void gates_kernel(
    const float* __restrict__ x,
    const float* __restrict__ fdw, const float* __restrict__ sdw,
    const float* __restrict__ fgw, const float* __restrict__ sgw,
    const float* __restrict__ fdb, const float* __restrict__ sdb,
    float* __restrict__ fd, float* __restrict__ sd,
    float* __restrict__ fg, float* __restrict__ sg)
{
    __shared__ float xs[64][68];
    __shared__ float ws[64][48];
    int t = threadIdx.x;
    int blk = blockIdx.x;
    int r = t >> 2, g = t & 3;
    float acc[12];
    #pragma unroll
    for (int j = 0; j < 12; j++) acc[j] = 0.f;

    for (int kt = 0; kt < HID; kt += 64) {
        #pragma unroll
        for (int u = 0; u < 4; u++) {
            int idx = u * 256 + t;
            int xr = idx >> 4, xq = idx & 15;
            float4 xv = *(const float4*)(x + (size_t)(blk * 64 + xr) * HID + kt + xq * 4);
            xs[xr][xq * 4 + 0] = xv.x; xs[xr][xq * 4 + 1] = xv.y;
            xs[xr][xq * 4 + 2] = xv.z; xs[xr][xq * 4 + 3] = xv.w;
        }
        #pragma unroll
        for (int u = 0; u < 12; u++) {
            int idx = u * 256 + t;
            int wk = idx / 48, wj = idx % 48;
            int m = wj / 12, jj = wj % 12;
            const float* W = (m == 0) ? fdw : (m == 1) ? sdw : (m == 2) ? fgw : sgw;
            ws[wk][wj] = W[(size_t)(kt + wk) * NH + jj];
        }
        __syncthreads();
        for (int kk = 0; kk < 64; kk++) {
            float xv = xs[r][kk];
            #pragma unroll
            for (int j = 0; j < 12; j++) acc[j] += xv * ws[kk][g * 12 + j];
        }
        __syncthreads();
    }
    int token = blk * 64 + r;
    int b = token >> 9, l = token & (LSEQ - 1);
    float* dst = (g == 0) ? fd : (g == 1) ? sd : (g == 2) ? fg : sg;
    #pragma unroll
    for (int j = 0; j < 12; j++) {
        float vv = acc[j];
        if (g == 0) vv += fdb[j];
        else if (g == 1) vv += sdb[j];
        vv = 1.0f / (1.0f + expf(-vv));
        dst[(size_t)(b * NH + j) * LSEQ + l] = vv;
    }
}

/* ---------------- chunk means of fd/sd ---------------- */
__global__ __launch_bounds__(256) void cmean_kernel(
    const float* __restrict__ fd, const float* __restrict__ sd,
    float* __restrict__ fdm, float* __restrict__ sdm)
{
    __shared__ float red[32];
    int bid = blockIdx.x;
    int bh = bid >> 1, c = bid & 1;
    int t = threadIdx.x;
    float a = fd[(size_t)bh * LSEQ + c * 256 + t];
    float b = sd[(size_t)bh * LSEQ + c * 256 + t];
    block_sum2(a, b, red);
    if (t == 0) { fdm[bid] = a * (1.f / 256.f); sdm[bid] = b * (1.f / 256.f); }
}

/* ---------------- delta rule: one 256-thread CTA per (b,h) ---------------- */
#define SPAD 257
#define QPAD 66
#define DELTA_SMEM_BYTES ((4*4096 + 2*16896 + 40) * 4)

__global__ __launch_bounds__(256, 1) void delta_kernel(
    const float* __restrict__ q, const float* __restrict__ k, const float* __restrict__ v,
    const float* __restrict__ fg, const float* __restrict__ sg,
    const float* __restrict__ fdm, const float* __restrict__ sdm,
    float* __restrict__ o)
{
    extern __shared__ float smf[];
    float* Sf = smf;
    float* Ss = Sf + 4096;
    float* G  = Ss + 4096;
    float* A  = G + 4096;
    float* T0 = A + 4096;
    float* T1 = T0 + 16896;
    float* red = T1 + 16896;

    int t = threadIdx.x;
    int bh = blockIdx.x;
    int b = bh / NH, h = bh % NH;
    int d = t >> 2, g = t & 3, e0 = g * 16;

    #pragma unroll
    for (int j = 0; j < 16; j++) { Sf[d * 64 + e0 + j] = 0.f; Ss[d * 64 + e0 + j] = 0.f; }
    __syncthreads();

    const float* qb = q + (size_t)bh * LSEQ * DH;
    const float* kb = k + (size_t)bh * LSEQ * DH;
    const float* vb = v + (size_t)bh * LSEQ * DH;

    for (int c = 0; c < 2; c++) {
        int c0 = c * 256;
        float df = powf(fdm[bh * 2 + c], 256.0f);
        float ds = powf(sdm[bh * 2 + c], 256.0f);

        float pf = 0.f, ps = 0.f;
        #pragma unroll
        for (int j = 0; j < 16; j++) {
            int idx = d * 64 + e0 + j;
            float a = Sf[idx] * df; Sf[idx] = a; pf += a * a;
            float bb = Ss[idx] * ds; Ss[idx] = bb; ps += bb * bb;
        }
        block_sum2(pf, ps, red);
        float rf = 1.0f / (sqrtf(pf) + 1e-8f);
        float rs = 1.0f / (sqrtf(ps) + 1e-8f);

        #pragma unroll
        for (int u = 0; u < 16; u++) {
            int idx4 = u * 256 + t;
            int r = idx4 >> 4, e4 = (idx4 & 15) * 4;
            float4 kv = *(const float4*)(kb + (size_t)(c0 + r) * DH + e4);
            T0[(e4 + 0) * SPAD + r] = kv.x; T0[(e4 + 1) * SPAD + r] = kv.y;
            T0[(e4 + 2) * SPAD + r] = kv.z; T0[(e4 + 3) * SPAD + r] = kv.w;
            float4 vv = *(const float4*)(vb + (size_t)(c0 + r) * DH + e4);
            T1[(e4 + 0) * SPAD + r] = vv.x; T1[(e4 + 1) * SPAD + r] = vv.y;
            T1[(e4 + 2) * SPAD + r] = vv.z; T1[(e4 + 3) * SPAD + r] = vv.w;
        }
        __syncthreads();

        {
            float accG[16], accA[16];
            #pragma unroll
            for (int j = 0; j < 16; j++) { accG[j] = 0.f; accA[j] = 0.f; }
            for (int r = 0; r < 256; r++) {
                float kd = T0[d * SPAD + r];
                #pragma unroll
                for (int j = 0; j < 16; j++) {
                    accG[j] += kd * T0[(e0 + j) * SPAD + r];
                    accA[j] += kd * T1[(e0 + j) * SPAD + r];
                }
            }
            #pragma unroll
            for (int j = 0; j < 16; j++) { G[d * 64 + e0 + j] = accG[j]; A[d * 64 + e0 + j] = accA[j]; }
        }
        __syncthreads();

        #pragma unroll
        for (int u = 0; u < 16; u++) {
            int idx4 = u * 256 + t;
            int r = idx4 >> 4, e4 = (idx4 & 15) * 4;
            float4 qv = *(const float4*)(qb + (size_t)(c0 + r) * DH + e4);
            T0[r * QPAD + e4 + 0] = qv.x; T0[r * QPAD + e4 + 1] = qv.y;
            T0[r * QPAD + e4 + 2] = qv.z; T0[r * QPAD + e4 + 3] = qv.w;
        }
        __syncthreads();

        {
            float of[16], os[16];
            #pragma unroll
            for (int j = 0; j < 16; j++) { of[j] = 0.f; os[j] = 0.f; }
            for (int kk = 0; kk < 64; kk++) {
                float qv = T0[d * QPAD + kk];
                #pragma unroll
                for (int j = 0; j < 16; j++) {
                    of[j] += qv * Sf[kk * 64 + e0 + j];
                    os[j] += qv * Ss[kk * 64 + e0 + j];
                }
            }
            float fgv = fg[(size_t)bh * LSEQ + c0 + d];
            float sgv = sg[(size_t)bh * LSEQ + c0 + d];
            float* orow = o + (size_t)(b * LSEQ + c0 + d) * HID + h * DH + e0;
            #pragma unroll
            for (int j = 0; j < 16; j++)
                orow[j] = 0.6f * fgv * of[j] * rf + 0.4f * sgv * os[j] * rs;
        }

        {
            float tf[16], ts[16];
            #pragma unroll
            for (int j = 0; j < 16; j++) { tf[j] = 0.f; ts[j] = 0.f; }
            for (int kk = 0; kk < 64; kk++) {
                float gv = G[d * 64 + kk];
                #pragma unroll
                for (int j = 0; j < 16; j++) {
                    tf[j] += gv * Sf[kk * 64 + e0 + j];
                    ts[j] += gv * Ss[kk * 64 + e0 + j];
                }
            }
            __syncthreads();
            float nf = 0.f, ns = 0.f;
            #pragma unroll
            for (int j = 0; j < 16; j++) {
                int idx = d * 64 + e0 + j;
                float sv = Sf[idx] + A[idx] - tf[j] * rf;
                Sf[idx] = sv; nf += sv * sv;
                float sw = Ss[idx] + A[idx] - ts[j] * rs;
                Ss[idx] = sw; ns += sw * sw;
            }
            block_sum2(nf, ns, red);
            float qf = 1.0f / (sqrtf(nf) + 1e-8f);
            float qs = 1.0f / (sqrtf(ns) + 1e-8f);
            #pragma unroll
            for (int j = 0; j < 16; j++) {
                int idx = d * 64 + e0 + j;
                Sf[idx] *= qf; Ss[idx] *= qs;
            }
            __syncthreads();
        }
    }
}

/* ---------------- per-(b,l,h) rms norm over d=64, in place ---------------- */
__global__ __launch_bounds__(256) void rms_kernel(float* __restrict__ o, const float* __restrict__ w)
{
    int warp = threadIdx.x >> 5, lane = threadIdx.x & 31;
    size_t row = (size_t)blockIdx.x * 8 + warp;
    float2* p = (float2*)(o + row * DH) + lane;
    float2 v = *p;
    float ss = v.x * v.x + v.y * v.y;
    #pragma unroll
    for (int off = 16; off > 0; off >>= 1) ss += __shfl_xor_sync(0xffffffffu, ss, off);
    float inv = 1.0f / sqrtf(ss * (1.f / 64.f) + 1e-6f);
    v.x = v.x * inv * w[lane * 2];
    v.y = v.y * inv * w[lane * 2 + 1];
    *p = v;
}

/* ---------------- host ---------------- */
static float* symf(const void* sym) { void* p = nullptr; cudaGetSymbolAddress(&p, sym); return (float*)p; }
static __nv_bfloat16* symb(const void* sym) { void* p = nullptr; cudaGetSymbolAddress(&p, sym); return (__nv_bfloat16*)p; }

extern "C" void kernel_launch(void* const* d_in, const int* in_sizes, int n_in,
                              void* d_out, int out_size)
{
    const int*   ids = (const int*)  d_in[0];
    const float* we  = (const float*)d_in[1];
    const float* te  = (const float*)d_in[2];
    const float* pe  = (const float*)d_in[3];
    const float* elw = (const float*)d_in[4];
    const float* elb = (const float*)d_in[5];
    const float* qw  = (const float*)d_in[6];
    const float* kw  = (const float*)d_in[7];
    const float* vw  = (const float*)d_in[8];
    const float* fdw = (const float*)d_in[9];
    const float* fdb = (const float*)d_in[10];
    const float* sdw = (const float*)d_in[11];
    const float* sdb = (const float*)d_in[12];
    const float* fgw = (const float*)d_in[13];
    const float* sgw = (const float*)d_in[14];
    const float* onw = (const float*)d_in[15];
    const float* ow  = (const float*)d_in[16];
    const float* alw = (const float*)d_in[17];
    const float* alb = (const float*)d_in[18];
    const float* w1  = (const float*)d_in[19];
    const float* b1  = (const float*)d_in[20];
    const float* w2  = (const float*)d_in[21];
    const float* b2  = (const float*)d_in[22];
    const float* flw = (const float*)d_in[23];
    const float* flb = (const float*)d_in[24];
    float* out = (float*)d_out;

    float* px  = symf(g_x);  float* pq  = symf(g_q);  float* pk  = symf(g_k);
    float* pv  = symf(g_v);  float* po  = symf(g_o);  float* py  = symf(g_y);
    float* ph  = symf(g_h);
    float* pfd = symf(g_fd); float* psd = symf(g_sd);
    float* pfg = symf(g_fg); float* psg = symf(g_sg);
    float* pfdm = symf(g_fdm); float* psdm = symf(g_sdm);
    __nv_bfloat16* pwh = symb(g_wth); __nv_bfloat16* pwl = symb(g_wtl);
    __nv_bfloat16* pah = symb(g_ah);  __nv_bfloat16* pal = symb(g_al);

    static bool attr_done = false;
    if (!attr_done) {
        cudaFuncSetAttribute(delta_kernel, cudaFuncAttributeMaxDynamicSharedMemorySize, DELTA_SMEM_BYTES);
        cudaFuncSetAttribute(gemm_bf3, cudaFuncAttributeMaxDynamicSharedMemorySize, GEMM_SMEM);
        attr_done = true;
    }

    /* weight transpose+split */
    dim3 tb(32, 8);
    for (int i = 0; i < NLAY; i++) {
        size_t base = (size_t)i * WLAYER;
        tsplit_kernel<<<dim3(HID/32, HID/32), tb>>>(qw + (size_t)i*WQKV, pwh + base,            pwl + base,            HID, HID);
        tsplit_kernel<<<dim3(HID/32, HID/32), tb>>>(kw + (size_t)i*WQKV, pwh + base + WQKV,     pwl + base + WQKV,     HID, HID);
        tsplit_kernel<<<dim3(HID/32, HID/32), tb>>>(vw + (size_t)i*WQKV, pwh + base + 2*WQKV,   pwl + base + 2*WQKV,   HID, HID);
        tsplit_kernel<<<dim3(HID/32, HID/32), tb>>>(ow + (size_t)i*WQKV, pwh + base + 3*WQKV,   pwl + base + 3*WQKV,   HID, HID);
        tsplit_kernel<<<dim3(FFND/32, HID/32), tb>>>(w1 + (size_t)i*WFFN, pwh + base + 4*WQKV,        pwl + base + 4*WQKV,        HID, FFND);
        tsplit_kernel<<<dim3(HID/32, FFND/32), tb>>>(w2 + (size_t)i*WFFN, pwh + base + 4*WQKV + WFFN, pwl + base + 4*WQKV + WFFN, FFND, HID);
    }

    embed_kernel<<<NTOK, 256>>>(ids, we, te, pe, elw, elb, px);

    dim3 gQ(HID / 128, NTOK / 128);
    dim3 gF1(FFND / 128, NTOK / 128);

    for (int i = 0; i < NLAY; i++) {
        size_t base = (size_t)i * WLAYER;

        split_kernel<<<(NTOK*HID)/1024, 256>>>((const float4*)px, (__nv_bfloat162*)pah, (__nv_bfloat162*)pal);
        gemm_bf3<<<gQ, 256, GEMM_SMEM>>>(pah, pal, pwh + base,          pwl + base,          pq, HID, HID, 1, nullptr);
        gemm_bf3<<<gQ, 256, GEMM_SMEM>>>(pah, pal, pwh + base + WQKV,   pwl + base + WQKV,   pk, HID, HID, 1, nullptr);
        gemm_bf3<<<gQ, 256, GEMM_SMEM>>>(pah, pal, pwh + base + 2*WQKV, pwl + base + 2*WQKV, pv, HID, HID, 1, nullptr);

        gates_kernel<<<NTOK / 64, 256>>>(px,
            fdw + (size_t)i * HID * NH, sdw + (size_t)i * HID * NH,
            fgw + (size_t)i * HID * NH, sgw + (size_t)i * HID * NH,
            fdb + (size_t)i * NH, sdb + (size_t)i * NH,
            pfd, psd, pfg, psg);

        cmean_kernel<<<BATCH * NH * 2, 256>>>(pfd, psd, pfdm, psdm);
        delta_kernel<<<BATCH * NH, 256, DELTA_SMEM_BYTES>>>(pq, pk, pv, pfg, psg, pfdm, psdm, po);
        rms_kernel<<<(NTOK * NH) / 8, 256>>>(po, onw + (size_t)i * DH);

        split_kernel<<<(NTOK*HID)/1024, 256>>>((const float4*)po, (__nv_bfloat162*)pah, (__nv_bfloat162*)pal);
        gemm_bf3<<<gQ, 256, GEMM_SMEM>>>(pah, pal, pwh + base + 3*WQKV, pwl + base + 3*WQKV, py, HID, HID, 0, nullptr);

        ln_res_kernel<<<NTOK, 256>>>(px, py, nullptr,
            alw + (size_t)i * HID, alb + (size_t)i * HID, px);

        split_kernel<<<(NTOK*HID)/1024, 256>>>((const float4*)px, (__nv_bfloat162*)pah, (__nv_bfloat162*)pal);
        gemm_bf3<<<gF1, 256, GEMM_SMEM>>>(pah, pal, pwh + base + 4*WQKV, pwl + base + 4*WQKV, ph, HID, FFND, 2, b1 + (size_t)i * FFND);

        split_kernel<<<(NTOK*FFND)/1024, 256>>>((const float4*)ph, (__nv_bfloat162*)pah, (__nv_bfloat162*)pal);
        gemm_bf3<<<gQ, 256, GEMM_SMEM>>>(pah, pal, pwh + base + 4*WQKV + WFFN, pwl + base + 4*WQKV + WFFN, py, FFND, HID, 0, nullptr);

        float* dst = (i == NLAY - 1) ? out : px;
        ln_res_kernel<<<NTOK, 256>>>(px, py, b2 + (size_t)i * HID,
            flw + (size_t)i * HID, flb + (size_t)i * HID, dst);
    }
}

// round 10
// speedup vs baseline: 2.0867x; 1.0174x over previous
#include <cuda_runtime.h>
#include <cuda_bf16.h>
#include <cstdint>

#define NH 12
#define DH 64
#define HID 768
#define LSEQ 512
#define BATCH 16
#define NTOK (BATCH*LSEQ)
#define FFND 3072
#define NLAY 6

#define WQKV (HID*HID)            /* 589824  */
#define WFFN (HID*FFND)           /* 2359296 */
#define WLAYER (4*WQKV + 2*WFFN)  /* 7077888 */

/* ---------------- scratch ---------------- */
__device__ float g_x [NTOK*HID];
__device__ float g_q [NTOK*HID];
__device__ float g_k [NTOK*HID];
__device__ float g_v [NTOK*HID];
__device__ float g_o [NTOK*HID];
__device__ float g_y [NTOK*HID];
__device__ float g_fd[BATCH*NH*LSEQ];
__device__ float g_sd[BATCH*NH*LSEQ];
__device__ float g_fg[BATCH*NH*LSEQ];
__device__ float g_sg[BATCH*NH*LSEQ];
__device__ float g_fdm[BATCH*NH*2];
__device__ float g_sdm[BATCH*NH*2];
__device__ __align__(16) __nv_bfloat16 g_wth[NLAY*WLAYER];
__device__ __align__(16) __nv_bfloat16 g_wtl[NLAY*WLAYER];
__device__ __align__(16) __nv_bfloat16 g_xh[NTOK*HID];
__device__ __align__(16) __nv_bfloat16 g_xl[NTOK*HID];
__device__ __align__(16) __nv_bfloat16 g_hh[NTOK*FFND];
__device__ __align__(16) __nv_bfloat16 g_hl[NTOK*FFND];

/* ---------------- PTX helpers (no arch-suffix instructions) ---------------- */
__device__ __forceinline__ uint32_t smem_u32(const void* p) {
    uint32_t a;
    asm("{ .reg .u64 t; cvta.to.shared.u64 t, %1; cvt.u32.u64 %0, t; }" : "=r"(a) : "l"(p));
    return a;
}
__device__ __forceinline__ void cp_async16(uint32_t saddr, const void* gaddr) {
    asm volatile("cp.async.cg.shared.global [%0], [%1], 16;" :: "r"(saddr), "l"(gaddr) : "memory");
}
__device__ __forceinline__ void cp_commit() {
    asm volatile("cp.async.commit_group;" ::: "memory");
}
template <int N>
__device__ __forceinline__ void cp_wait() {
    asm volatile("cp.async.wait_group %0;" :: "n"(N) : "memory");
}
__device__ __forceinline__ void ldsm_x4(uint32_t* r, uint32_t a) {
    asm volatile("ldmatrix.sync.aligned.m8n8.x4.shared.b16 {%0,%1,%2,%3}, [%4];"
        : "=r"(r[0]), "=r"(r[1]), "=r"(r[2]), "=r"(r[3]) : "r"(a));
}
__device__ __forceinline__ void mma16816(float* d, const uint32_t* a, const uint32_t* b) {
    asm volatile("mma.sync.aligned.m16n8k16.row.col.f32.bf16.bf16.f32 "
        "{%0,%1,%2,%3}, {%4,%5,%6,%7}, {%8,%9}, {%0,%1,%2,%3};"
        : "+f"(d[0]), "+f"(d[1]), "+f"(d[2]), "+f"(d[3])
        : "r"(a[0]), "r"(a[1]), "r"(a[2]), "r"(a[3]), "r"(b[0]), "r"(b[1]));
}

/* ---------------- block reductions (blockDim=256) ---------------- */
__device__ __forceinline__ float block_sum1(float a, float* red) {
    #pragma unroll
    for (int off = 16; off > 0; off >>= 1) a += __shfl_xor_sync(0xffffffffu, a, off);
    int t = threadIdx.x;
    if ((t & 31) == 0) red[t >> 5] = a;
    __syncthreads();
    if (t == 0) {
        float s = 0.f;
        #pragma unroll
        for (int i = 0; i < 8; i++) s += red[i];
        red[8] = s;
    }
    __syncthreads();
    return red[8];
}

__device__ __forceinline__ void block_sum2(float& a, float& b, float* red) {
    #pragma unroll
    for (int off = 16; off > 0; off >>= 1) {
        a += __shfl_xor_sync(0xffffffffu, a, off);
        b += __shfl_xor_sync(0xffffffffu, b, off);
    }
    int t = threadIdx.x;
    if ((t & 31) == 0) { red[t >> 5] = a; red[8 + (t >> 5)] = b; }
    __syncthreads();
    if (t == 0) {
        float sa = 0.f, sb = 0.f;
        #pragma unroll
        for (int i = 0; i < 8; i++) { sa += red[i]; sb += red[8 + i]; }
        red[16] = sa; red[17] = sb;
    }
    __syncthreads();
    a = red[16]; b = red[17];
}

__device__ __forceinline__ void split_write(
    __nv_bfloat16* __restrict__ oh, __nv_bfloat16* __restrict__ ol, size_t idx, float v)
{
    __nv_bfloat16 hv = __float2bfloat16(v);
    oh[idx] = hv;
    ol[idx] = __float2bfloat16(v - __bfloat162float(hv));
}

/* ---------------- embedding + LN (+ bf16 hi/lo split) ---------------- */
__global__ __launch_bounds__(256) void embed_kernel(
    const int* __restrict__ ids, const float* __restrict__ we,
    const float* __restrict__ te, const float* __restrict__ pe,
    const float* __restrict__ lw, const float* __restrict__ lb,
    float* __restrict__ x, __nv_bfloat16* __restrict__ xh, __nv_bfloat16* __restrict__ xl)
{
    __shared__ float buf[HID];
    __shared__ float red[32];
    int row = blockIdx.x, t = threadIdx.x;
    int l = row & (LSEQ - 1);
    int id = ids[row];
    float s = 0.f;
    for (int j = t; j < HID; j += 256) {
        float v = we[(size_t)id * HID + j] + te[j] + pe[(size_t)l * HID + j];
        buf[j] = v; s += v;
    }
    float mean = block_sum1(s, red) * (1.f / HID);
    float vs = 0.f;
    for (int j = t; j < HID; j += 256) { float d = buf[j] - mean; vs += d * d; }
    float var = block_sum1(vs, red) * (1.f / HID);
    float inv = 1.0f / sqrtf(var + 1e-12f);
    for (int j = t; j < HID; j += 256) {
        float v = (buf[j] - mean) * inv * lw[j] + lb[j];
        x[(size_t)row * HID + j] = v;
        split_write(xh, xl, (size_t)row * HID + j, v);
    }
}

/* ---------------- residual + optional bias + LN (+ optional split) ---------------- */
__global__ __launch_bounds__(256) void ln_res_kernel(
    const float* __restrict__ resid, const float* __restrict__ y,
    const float* __restrict__ bias, const float* __restrict__ w,
    const float* __restrict__ bp, float* __restrict__ out,
    __nv_bfloat16* __restrict__ oh, __nv_bfloat16* __restrict__ ol)
{
    __shared__ float buf[HID];
    __shared__ float red[32];
    int row = blockIdx.x, t = threadIdx.x;
    float s = 0.f;
    for (int j = t; j < HID; j += 256) {
        float v = resid[(size_t)row * HID + j] + y[(size_t)row * HID + j];
        if (bias) v += bias[j];
        buf[j] = v; s += v;
    }
    float mean = block_sum1(s, red) * (1.f / HID);
    float vs = 0.f;
    for (int j = t; j < HID; j += 256) { float d = buf[j] - mean; vs += d * d; }
    float var = block_sum1(vs, red) * (1.f / HID);
    float inv = 1.0f / sqrtf(var + 1e-12f);
    for (int j = t; j < HID; j += 256) {
        float v = (buf[j] - mean) * inv * w[j] + bp[j];
        out[(size_t)row * HID + j] = v;
        if (oh) split_write(oh, ol, (size_t)row * HID + j, v);
    }
}

/* ---------------- weight transpose + split: W[K,N] -> Th,Tl[N,K] bf16 ---------------- */
__global__ void tsplit_kernel(const float* __restrict__ W,
                              __nv_bfloat16* __restrict__ Th, __nv_bfloat16* __restrict__ Tl,
                              int K, int N)
{
    __shared__ float tile[32][33];
    int k0 = blockIdx.y * 32, n0 = blockIdx.x * 32;
    int tx = threadIdx.x, ty = threadIdx.y;
    #pragma unroll
    for (int j = 0; j < 4; j++)
        tile[ty + 8*j][tx] = W[(size_t)(k0 + ty + 8*j) * N + n0 + tx];
    __syncthreads();
    #pragma unroll
    for (int j = 0; j < 4; j++) {
        int n = n0 + ty + 8*j, k = k0 + tx;
        float v = tile[tx][ty + 8*j];
        __nv_bfloat16 hv = __float2bfloat16(v);
        Th[(size_t)n * K + k] = hv;
        Tl[(size_t)n * K + k] = __float2bfloat16(v - __bfloat162float(hv));
    }
}

/* ---------------- bf16x3 warp-MMA GEMM: C[M,N] = A[M,K] @ Bt[N,K]^T ----------------
   epi: 0 plain fp32 C; 1 silu + scatter to Cq/Ck/Cv [b,h,l,d] (N=2304 packed QKV);
   2 gelu(v+bias) -> bf16 hi/lo H,L. */
#define BK 32
#define LDS 40                    /* bf16 row stride in smem (80B) */
#define ARR_ELEM (128*LDS)        /* 5120 bf16 per array */
#define STAGE_ELEM (4*ARR_ELEM)   /* 20480 bf16 per stage */
#define GEMM_SMEM (2*STAGE_ELEM*2)/* 81920 bytes */

__global__ __launch_bounds__(256) void gemm_bf3(
    const __nv_bfloat16* __restrict__ Ah, const __nv_bfloat16* __restrict__ Al,
    const __nv_bfloat16* __restrict__ Bh, const __nv_bfloat16* __restrict__ Bl,
    int K, int N, int epi, const float* __restrict__ bias,
    float* __restrict__ C, float* __restrict__ Cq, float* __restrict__ Ck, float* __restrict__ Cv,
    __nv_bfloat16* __restrict__ H, __nv_bfloat16* __restrict__ L)
{
    extern __shared__ __nv_bfloat16 smem[];
    uint32_t smb = smem_u32(smem);
    int tid = threadIdx.x, lane = tid & 31, wid = tid >> 5;
    int bx = blockIdx.x, by = blockIdx.y;
    int wy = wid >> 2, wx = wid & 3;
    int m0 = wy * 64, n0 = wx * 32;

    const char* gsrc[4] = {
        (const char*)(Ah + (size_t)(by * 128) * K),
        (const char*)(Al + (size_t)(by * 128) * K),
        (const char*)(Bh + (size_t)(bx * 128) * K),
        (const char*)(Bl + (size_t)(bx * 128) * K)
    };

    int r0 = tid >> 2, cq = tid & 3;
    int r1 = r0 + 64;

    float acc[4][4][4];
    #pragma unroll
    for (int mt = 0; mt < 4; mt++)
        #pragma unroll
        for (int nt = 0; nt < 4; nt++)
            #pragma unroll
            for (int e = 0; e < 4; e++) acc[mt][nt][e] = 0.f;

    int NKB = K / BK;

    /* prefetch slab 0 into stage 0 */
    {
        #pragma unroll
        for (int m = 0; m < 4; m++) {
            uint32_t sb = smb + (uint32_t)(m * ARR_ELEM) * 2;
            cp_async16(sb + (uint32_t)(r0 * LDS + cq * 8) * 2, gsrc[m] + (size_t)r0 * K * 2 + cq * 16);
            cp_async16(sb + (uint32_t)(r1 * LDS + cq * 8) * 2, gsrc[m] + (size_t)r1 * K * 2 + cq * 16);
        }
        cp_commit();
    }

    /* ldmatrix lane addressing */
    int aj = lane >> 3;
    int arow = ((aj & 1) << 3) + (lane & 7);
    int acol = (aj >> 1) << 3;
    int brow = ((aj >> 1) << 3) + (lane & 7);   /* B x4: rows for matrix pair */
    int bcol = (aj & 1) << 3;

    for (int kb = 0; kb < NKB; kb++) {
        int s = kb & 1;
        if (kb + 1 < NKB) {
            int s2 = s ^ 1;
            int koff = (kb + 1) * (BK * 2);
            #pragma unroll
            for (int m = 0; m < 4; m++) {
                uint32_t sb = smb + (uint32_t)(s2 * STAGE_ELEM + m * ARR_ELEM) * 2;
                cp_async16(sb + (uint32_t)(r0 * LDS + cq * 8) * 2, gsrc[m] + (size_t)r0 * K * 2 + koff + cq * 16);
                cp_async16(sb + (uint32_t)(r1 * LDS + cq * 8) * 2, gsrc[m] + (size_t)r1 * K * 2 + koff + cq * 16);
            }
            cp_commit();
            cp_wait<1>();
        } else {
            cp_wait<0>();
        }
        __syncthreads();

        uint32_t stb = smb + (uint32_t)(s * STAGE_ELEM) * 2;
        uint32_t aAh = stb;
        uint32_t aAl = stb + (uint32_t)ARR_ELEM * 2;
        uint32_t aBh = stb + (uint32_t)(2 * ARR_ELEM) * 2;
        uint32_t aBl = stb + (uint32_t)(3 * ARR_ELEM) * 2;

        #pragma unroll
        for (int ks = 0; ks < 2; ks++) {
            int kc = ks * 16;
            uint32_t ah[4][4], al[4][4];
            #pragma unroll
            for (int mt = 0; mt < 4; mt++) {
                uint32_t off = (uint32_t)((m0 + mt * 16 + arow) * LDS + kc + acol) * 2;
                ldsm_x4(ah[mt], aAh + off);
                ldsm_x4(al[mt], aAl + off);
            }
            #pragma unroll
            for (int p = 0; p < 2; p++) {
                uint32_t boff = (uint32_t)((n0 + p * 16 + brow) * LDS + kc + bcol) * 2;
                uint32_t bh4[4], bl4[4];
                ldsm_x4(bh4, aBh + boff);
                ldsm_x4(bl4, aBl + boff);
                #pragma unroll
                for (int sub = 0; sub < 2; sub++) {
                    int nt = p * 2 + sub;
                    #pragma unroll
                    for (int mt = 0; mt < 4; mt++) {
                        mma16816(acc[mt][nt], ah[mt], bh4 + sub * 2);
                        mma16816(acc[mt][nt], ah[mt], bl4 + sub * 2);
                        mma16816(acc[mt][nt], al[mt], bh4 + sub * 2);
                    }
                }
            }
        }
        __syncthreads();
    }

    /* epilogue */
    int gm0 = by * 128 + m0;
    int gn0 = bx * 128 + n0;
    #pragma unroll
    for (int mt = 0; mt < 4; mt++) {
        #pragma unroll
        for (int nt = 0; nt < 4; nt++) {
            int row0 = gm0 + mt * 16 + (lane >> 2);
            int col0 = gn0 + nt * 8 + (lane & 3) * 2;
            if (epi == 2) {
                #pragma unroll
                for (int half = 0; half < 2; half++) {
                    int row = row0 + half * 8;
                    float v0 = acc[mt][nt][half * 2 + 0] + bias[col0];
                    float v1 = acc[mt][nt][half * 2 + 1] + bias[col0 + 1];
                    v0 = 0.5f * v0 * (1.0f + erff(v0 * 0.70710678118654752f));
                    v1 = 0.5f * v1 * (1.0f + erff(v1 * 0.70710678118654752f));
                    __nv_bfloat16 h0 = __float2bfloat16(v0);
                    __nv_bfloat16 h1 = __float2bfloat16(v1);
                    *(__nv_bfloat162*)(H + (size_t)row * N + col0) = __nv_bfloat162(h0, h1);
                    *(__nv_bfloat162*)(L + (size_t)row * N + col0) =
                        __nv_bfloat162(__float2bfloat16(v0 - __bfloat162float(h0)),
                                       __float2bfloat16(v1 - __bfloat162float(h1)));
                }
            } else {
                #pragma unroll
                for (int e = 0; e < 4; e++) {
                    int row = row0 + ((e >> 1) << 3);
                    int col = col0 + (e & 1);
                    float v = acc[mt][nt][e];
                    if (epi == 1) {
                        float sv = v / (1.0f + expf(-v));
                        int m = col / HID, cc = col - m * HID;
                        float* dst = (m == 0) ? Cq : (m == 1) ? Ck : Cv;
                        int b_ = row >> 9, l = row & (LSEQ - 1);
                        int h = cc >> 6, d = cc & 63;
                        dst[(size_t)((b_ * NH + h) * LSEQ + l) * DH + d] = sv;
                    } else {
                        C[(size_t)row * N + col] = v;
                    }
                }
            }
        }
    }
}

/* ---------------- gates: 4x [8192,768]@[768,12] + sigmoid -> [b,h,l] ---------------- */
__global__ __launch_bounds__(256) void gates_kernel(
    const float* __restrict__ x,
    const float* __restrict__ fdw, const float* __restrict__ sdw,
    const float* __restrict__ fgw, const float* __restrict__ sgw,
    const float* __restrict__ fdb, const float* __restrict__ sdb,
    float* __restrict__ fd, float* __restrict__ sd,
    float* __restrict__ fg, float* __restrict__ sg)
{
    __shared__ float xs[64][68];
    __shared__ float ws[64][48];
    int t = threadIdx.x;
    int blk = blockIdx.x;
    int r = t >> 2, g = t & 3;
    float acc[12];
    #pragma unroll
    for (int j = 0; j < 12; j++) acc[j] = 0.f;

    for (int kt = 0; kt < HID; kt += 64) {
        #pragma unroll
        for (int u = 0; u < 4; u++) {
            int idx = u * 256 + t;
            int xr = idx >> 4, xq = idx & 15;
            float4 xv = *(const float4*)(x + (size_t)(blk * 64 + xr) * HID + kt + xq * 4);
            xs[xr][xq * 4 + 0] = xv.x; xs[xr][xq * 4 + 1] = xv.y;
            xs[xr][xq * 4 + 2] = xv.z; xs[xr][xq * 4 + 3] = xv.w;
        }
        #pragma unroll
        for (int u = 0; u < 12; u++) {
            int idx = u * 256 + t;
            int wk = idx / 48, wj = idx % 48;
            int m = wj / 12, jj = wj % 12;
            const float* W = (m == 0) ? fdw : (m == 1) ? sdw : (m == 2) ? fgw : sgw;
            ws[wk][wj] = W[(size_t)(kt + wk) * NH + jj];
        }
        __syncthreads();
        for (int kk = 0; kk < 64; kk++) {
            float xv = xs[r][kk];
            #pragma unroll
            for (int j = 0; j < 12; j++) acc[j] += xv * ws[kk][g * 12 + j];
        }
        __syncthreads();
    }
    int token = blk * 64 + r;
    int b = token >> 9, l = token & (LSEQ - 1);
    float* dst = (g == 0) ? fd : (g == 1) ? sd : (g == 2) ? fg : sg;
    #pragma unroll
    for (int j = 0; j < 12; j++) {
        float vv = acc[j];
        if (g == 0) vv += fdb[j];
        else if (g == 1) vv += sdb[j];
        vv = 1.0f / (1.0f + expf(-vv));
        dst[(size_t)(b * NH + j) * LSEQ + l] = vv;
    }
}

/* ---------------- chunk means of fd/sd ---------------- */
__global__ __launch_bounds__(256) void cmean_kernel(
    const float* __restrict__ fd, const float* __restrict__ sd,
    float* __restrict__ fdm, float* __restrict__ sdm)
{
    __shared__ float red[32];
    int bid = blockIdx.x;
    int bh = bid >> 1, c = bid & 1;
    int t = threadIdx.x;
    float a = fd[(size_t)bh * LSEQ + c * 256 + t];
    float b = sd[(size_t)bh * LSEQ + c * 256 + t];
    block_sum2(a, b, red);
    if (t == 0) { fdm[bid] = a * (1.f / 256.f); sdm[bid] = b * (1.f / 256.f); }
}

/* ---------------- delta rule: one 256-thread CTA per (b,h) ---------------- */
#define SPAD 257
#define QPAD 66
#define DELTA_SMEM_BYTES ((4*4096 + 2*16896 + 40) * 4)

__global__ __launch_bounds__(256, 1) void delta_kernel(
    const float* __restrict__ q, const float* __restrict__ k, const float* __restrict__ v,
    const float* __restrict__ fg, const float* __restrict__ sg,
    const float* __restrict__ fdm, const float* __restrict__ sdm,
    float* __restrict__ o)
{
    extern __shared__ float smf[];
    float* Sf = smf;
    float* Ss = Sf + 4096;
    float* G  = Ss + 4096;
    float* A  = G + 4096;
    float* T0 = A + 4096;
    float* T1 = T0 + 16896;
    float* red = T1 + 16896;

    int t = threadIdx.x;
    int bh = blockIdx.x;
    int b = bh / NH, h = bh % NH;
    int d = t >> 2, g = t & 3, e0 = g * 16;

    #pragma unroll
    for (int j = 0; j < 16; j++) { Sf[d * 64 + e0 + j] = 0.f; Ss[d * 64 + e0 + j] = 0.f; }
    __syncthreads();

    const float* qb = q + (size_t)bh * LSEQ * DH;
    const float* kb = k + (size_t)bh * LSEQ * DH;
    const float* vb = v + (size_t)bh * LSEQ * DH;

    for (int c = 0; c < 2; c++) {
        int c0 = c * 256;
        float df = powf(fdm[bh * 2 + c], 256.0f);
        float ds = powf(sdm[bh * 2 + c], 256.0f);

        float pf = 0.f, ps = 0.f;
        #pragma unroll
        for (int j = 0; j < 16; j++) {
            int idx = d * 64 + e0 + j;
            float a = Sf[idx] * df; Sf[idx] = a; pf += a * a;
            float bb = Ss[idx] * ds; Ss[idx] = bb; ps += bb * bb;
        }
        block_sum2(pf, ps, red);
        float rf = 1.0f / (sqrtf(pf) + 1e-8f);
        float rs = 1.0f / (sqrtf(ps) + 1e-8f);

        #pragma unroll
        for (int u = 0; u < 16; u++) {
            int idx4 = u * 256 + t;
            int r = idx4 >> 4, e4 = (idx4 & 15) * 4;
            float4 kv = *(const float4*)(kb + (size_t)(c0 + r) * DH + e4);
            T0[(e4 + 0) * SPAD + r] = kv.x; T0[(e4 + 1) * SPAD + r] = kv.y;
            T0[(e4 + 2) * SPAD + r] = kv.z; T0[(e4 + 3) * SPAD + r] = kv.w;
            float4 vv = *(const float4*)(vb + (size_t)(c0 + r) * DH + e4);
            T1[(e4 + 0) * SPAD + r] = vv.x; T1[(e4 + 1) * SPAD + r] = vv.y;
            T1[(e4 + 2) * SPAD + r] = vv.z; T1[(e4 + 3) * SPAD + r] = vv.w;
        }
        __syncthreads();

        {
            float accG[16], accA[16];
            #pragma unroll
            for (int j = 0; j < 16; j++) { accG[j] = 0.f; accA[j] = 0.f; }
            for (int r = 0; r < 256; r++) {
                float kd = T0[d * SPAD + r];
                #pragma unroll
                for (int j = 0; j < 16; j++) {
                    accG[j] += kd * T0[(e0 + j) * SPAD + r];
                    accA[j] += kd * T1[(e0 + j) * SPAD + r];
                }
            }
            #pragma unroll
            for (int j = 0; j < 16; j++) { G[d * 64 + e0 + j] = accG[j]; A[d * 64 + e0 + j] = accA[j]; }
        }
        __syncthreads();

        #pragma unroll
        for (int u = 0; u < 16; u++) {
            int idx4 = u * 256 + t;
            int r = idx4 >> 4, e4 = (idx4 & 15) * 4;
            float4 qv = *(const float4*)(qb + (size_t)(c0 + r) * DH + e4);
            T0[r * QPAD + e4 + 0] = qv.x; T0[r * QPAD + e4 + 1] = qv.y;
            T0[r * QPAD + e4 + 2] = qv.z; T0[r * QPAD + e4 + 3] = qv.w;
        }
        __syncthreads();

        {
            float of[16], os[16];
            #pragma unroll
            for (int j = 0; j < 16; j++) { of[j] = 0.f; os[j] = 0.f; }
            for (int kk = 0; kk < 64; kk++) {
                float qv = T0[d * QPAD + kk];
                #pragma unroll
                for (int j = 0; j < 16; j++) {
                    of[j] += qv * Sf[kk * 64 + e0 + j];
                    os[j] += qv * Ss[kk * 64 + e0 + j];
                }
            }
            float fgv = fg[(size_t)bh * LSEQ + c0 + d];
            float sgv = sg[(size_t)bh * LSEQ + c0 + d];
            float* orow = o + (size_t)(b * LSEQ + c0 + d) * HID + h * DH + e0;
            #pragma unroll
            for (int j = 0; j < 16; j++)
                orow[j] = 0.6f * fgv * of[j] * rf + 0.4f * sgv * os[j] * rs;
        }

        {
            float tf[16], ts[16];
            #pragma unroll
            for (int j = 0; j < 16; j++) { tf[j] = 0.f; ts[j] = 0.f; }
            for (int kk = 0; kk < 64; kk++) {
                float gv = G[d * 64 + kk];
                #pragma unroll
                for (int j = 0; j < 16; j++) {
                    tf[j] += gv * Sf[kk * 64 + e0 + j];
                    ts[j] += gv * Ss[kk * 64 + e0 + j];
                }
            }
            __syncthreads();
            float nf = 0.f, ns = 0.f;
            #pragma unroll
            for (int j = 0; j < 16; j++) {
                int idx = d * 64 + e0 + j;
                float sv = Sf[idx] + A[idx] - tf[j] * rf;
                Sf[idx] = sv; nf += sv * sv;
                float sw = Ss[idx] + A[idx] - ts[j] * rs;
                Ss[idx] = sw; ns += sw * sw;
            }
            block_sum2(nf, ns, red);
            float qf = 1.0f / (sqrtf(nf) + 1e-8f);
            float qs = 1.0f / (sqrtf(ns) + 1e-8f);
            #pragma unroll
            for (int j = 0; j < 16; j++) {
                int idx = d * 64 + e0 + j;
                Sf[idx] *= qf; Ss[idx] *= qs;
            }
            __syncthreads();
        }
    }
}

/* ---------------- per-(b,l,h) rms norm over d=64 -> bf16 hi/lo ---------------- */
__global__ __launch_bounds__(256) void rms_kernel(
    const float* __restrict__ o, const float* __restrict__ w,
    __nv_bfloat16* __restrict__ oh, __nv_bfloat16* __restrict__ ol)
{
    int warp = threadIdx.x >> 5, lane = threadIdx.x & 31;
    size_t row = (size_t)blockIdx.x * 8 + warp;
    const float2* p = (const float2*)(o + row * DH) + lane;
    float2 v = *p;
    float ss = v.x * v.x + v.y * v.y;
    #pragma unroll
    for (int off = 16; off > 0; off >>= 1) ss += __shfl_xor_sync(0xffffffffu, ss, off);
    float inv = 1.0f / sqrtf(ss * (1.f / 64.f) + 1e-6f);
    float v0 = v.x * inv * w[lane * 2];
    float v1 = v.y * inv * w[lane * 2 + 1];
    __nv_bfloat16 h0 = __float2bfloat16(v0);
    __nv_bfloat16 h1 = __float2bfloat16(v1);
    ((__nv_bfloat162*)(oh + row * DH))[lane] = __nv_bfloat162(h0, h1);
    ((__nv_bfloat162*)(ol + row * DH))[lane] =
        __nv_bfloat162(__float2bfloat16(v0 - __bfloat162float(h0)),
                       __float2bfloat16(v1 - __bfloat162float(h1)));
}

/* ---------------- host ---------------- */
static float* symf(const void* sym) { void* p = nullptr; cudaGetSymbolAddress(&p, sym); return (float*)p; }
static __nv_bfloat16* symb(const void* sym) { void* p = nullptr; cudaGetSymbolAddress(&p, sym); return (__nv_bfloat16*)p; }

extern "C" void kernel_launch(void* const* d_in, const int* in_sizes, int n_in,
                              void* d_out, int out_size)
{
    const int*   ids = (const int*)  d_in[0];
    const float* we  = (const float*)d_in[1];
    const float* te  = (const float*)d_in[2];
    const float* pe  = (const float*)d_in[3];
    const float* elw = (const float*)d_in[4];
    const float* elb = (const float*)d_in[5];
    const float* qw  = (const float*)d_in[6];
    const float* kw  = (const float*)d_in[7];
    const float* vw  = (const float*)d_in[8];
    const float* fdw = (const float*)d_in[9];
    const float* fdb = (const float*)d_in[10];
    const float* sdw = (const float*)d_in[11];
    const float* sdb = (const float*)d_in[12];
    const float* fgw = (const float*)d_in[13];
    const float* sgw = (const float*)d_in[14];
    const float* onw = (const float*)d_in[15];
    const float* ow  = (const float*)d_in[16];
    const float* alw = (const float*)d_in[17];
    const float* alb = (const float*)d_in[18];
    const float* w1  = (const float*)d_in[19];
    const float* b1  = (const float*)d_in[20];
    const float* w2  = (const float*)d_in[21];
    const float* b2  = (const float*)d_in[22];
    const float* flw = (const float*)d_in[23];
    const float* flb = (const float*)d_in[24];
    float* out = (float*)d_out;

    float* px  = symf(g_x);  float* pq  = symf(g_q);  float* pk  = symf(g_k);
    float* pv  = symf(g_v);  float* po  = symf(g_o);  float* py  = symf(g_y);
    float* pfd = symf(g_fd); float* psd = symf(g_sd);
    float* pfg = symf(g_fg); float* psg = symf(g_sg);
    float* pfdm = symf(g_fdm); float* psdm = symf(g_sdm);
    __nv_bfloat16* pwh = symb(g_wth); __nv_bfloat16* pwl = symb(g_wtl);
    __nv_bfloat16* pxh = symb(g_xh);  __nv_bfloat16* pxl = symb(g_xl);
    __nv_bfloat16* phh = symb(g_hh);  __nv_bfloat16* phl = symb(g_hl);

    static bool attr_done = false;
    if (!attr_done) {
        cudaFuncSetAttribute(delta_kernel, cudaFuncAttributeMaxDynamicSharedMemorySize, DELTA_SMEM_BYTES);
        cudaFuncSetAttribute(gemm_bf3, cudaFuncAttributeMaxDynamicSharedMemorySize, GEMM_SMEM);
        attr_done = true;
    }

    /* weight transpose+split (QKV packed contiguously -> one N=2304 matrix) */
    dim3 tb(32, 8);
    for (int i = 0; i < NLAY; i++) {
        size_t base = (size_t)i * WLAYER;
        tsplit_kernel<<<dim3(HID/32, HID/32), tb>>>(qw + (size_t)i*WQKV, pwh + base,            pwl + base,            HID, HID);
        tsplit_kernel<<<dim3(HID/32, HID/32), tb>>>(kw + (size_t)i*WQKV, pwh + base + WQKV,     pwl + base + WQKV,     HID, HID);
        tsplit_kernel<<<dim3(HID/32, HID/32), tb>>>(vw + (size_t)i*WQKV, pwh + base + 2*WQKV,   pwl + base + 2*WQKV,   HID, HID);
        tsplit_kernel<<<dim3(HID/32, HID/32), tb>>>(ow + (size_t)i*WQKV, pwh + base + 3*WQKV,   pwl + base + 3*WQKV,   HID, HID);
        tsplit_kernel<<<dim3(FFND/32, HID/32), tb>>>(w1 + (size_t)i*WFFN, pwh + base + 4*WQKV,        pwl + base + 4*WQKV,        HID, FFND);
        tsplit_kernel<<<dim3(HID/32, FFND/32), tb>>>(w2 + (size_t)i*WFFN, pwh + base + 4*WQKV + WFFN, pwl + base + 4*WQKV + WFFN, FFND, HID);
    }

    embed_kernel<<<NTOK, 256>>>(ids, we, te, pe, elw, elb, px, pxh, pxl);

    dim3 gQKV(3*HID / 128, NTOK / 128);
    dim3 gO(HID / 128, NTOK / 128);
    dim3 gF1(FFND / 128, NTOK / 128);

    for (int i = 0; i < NLAY; i++) {
        size_t base = (size_t)i * WLAYER;

        /* fused QKV: N = 2304 */
        gemm_bf3<<<gQKV, 256, GEMM_SMEM>>>(pxh, pxl, pwh + base, pwl + base,
            HID, 3*HID, 1, nullptr, nullptr, pq, pk, pv, nullptr, nullptr);

        gates_kernel<<<NTOK / 64, 256>>>(px,
            fdw + (size_t)i * HID * NH, sdw + (size_t)i * HID * NH,
            fgw + (size_t)i * HID * NH, sgw + (size_t)i * HID * NH,
            fdb + (size_t)i * NH, sdb + (size_t)i * NH,
            pfd, psd, pfg, psg);

        cmean_kernel<<<BATCH * NH * 2, 256>>>(pfd, psd, pfdm, psdm);
        delta_kernel<<<BATCH * NH, 256, DELTA_SMEM_BYTES>>>(pq, pk, pv, pfg, psg, pfdm, psdm, po);
        /* rms writes bf16 hi/lo directly into x-split buffers (x-split already consumed) */
        rms_kernel<<<(NTOK * NH) / 8, 256>>>(po, onw + (size_t)i * DH, pxh, pxl);

        gemm_bf3<<<gO, 256, GEMM_SMEM>>>(pxh, pxl, pwh + base + 3*WQKV, pwl + base + 3*WQKV,
            HID, HID, 0, nullptr, py, nullptr, nullptr, nullptr, nullptr, nullptr);

        ln_res_kernel<<<NTOK, 256>>>(px, py, nullptr,
            alw + (size_t)i * HID, alb + (size_t)i * HID, px, pxh, pxl);

        /* FFN1: gelu -> bf16 hi/lo directly */
        gemm_bf3<<<gF1, 256, GEMM_SMEM>>>(pxh, pxl, pwh + base + 4*WQKV, pwl + base + 4*WQKV,
            HID, FFND, 2, b1 + (size_t)i * FFND, nullptr, nullptr, nullptr, nullptr, phh, phl);

        gemm_bf3<<<gO, 256, GEMM_SMEM>>>(phh, phl, pwh + base + 4*WQKV + WFFN, pwl + base + 4*WQKV + WFFN,
            FFND, HID, 0, nullptr, py, nullptr, nullptr, nullptr, nullptr, nullptr);

        float* dst = (i == NLAY - 1) ? out : px;
        __nv_bfloat16* doh = (i == NLAY - 1) ? nullptr : pxh;
        __nv_bfloat16* dol = (i == NLAY - 1) ? nullptr : pxl;
        ln_res_kernel<<<NTOK, 256>>>(px, py, b2 + (size_t)i * HID,
            flw + (size_t)i * HID, flb + (size_t)i * HID, dst, doh, dol);
    }
}

// round 11
// speedup vs baseline: 2.8713x; 1.3760x over previous
#include <cuda_runtime.h>
#include <cuda_fp16.h>
#include <cstdint>

#define NH 12
#define DH 64
#define HID 768
#define LSEQ 512
#define BATCH 16
#define NTOK (BATCH*LSEQ)
#define FFND 3072
#define NLAY 6

#define WQKV (HID*HID)
#define WFFN (HID*FFND)
#define WLAYER (4*WQKV + 2*WFFN)

__device__ float g_x [NTOK*HID];
__device__ float g_q [NTOK*HID];
__device__ float g_k [NTOK*HID];
__device__ float g_v [NTOK*HID];
__device__ float g_o [NTOK*HID];
__device__ float g_y [NTOK*HID];
__device__ float g_fd[BATCH*NH*LSEQ];
__device__ float g_sd[BATCH*NH*LSEQ];
__device__ float g_fg[BATCH*NH*LSEQ];
__device__ float g_sg[BATCH*NH*LSEQ];
__device__ float g_fdm[BATCH*NH*2];
__device__ float g_sdm[BATCH*NH*2];
__device__ __align__(16) __half g_wh[NLAY*WLAYER];
__device__ __align__(16) __half g_xh[NTOK*(HID+FFND)];
__device__ __align__(16) __half g_xl[NTOK*(HID+FFND)];

__device__ __forceinline__ uint32_t smem_u32(const void* p) {
    uint32_t a;
    asm("{ .reg .u64 t; cvta.to.shared.u64 t, %1; cvt.u32.u64 %0, t; }" : "=r"(a) : "l"(p));
    return a;
}
__device__ __forceinline__ void cp_async16(uint32_t saddr, const void* gaddr) {
    asm volatile("cp.async.cg.shared.global [%0], [%1], 16;" :: "r"(saddr), "l"(gaddr) : "memory");
}
__device__ __forceinline__ void cp_commit() {
    asm volatile("cp.async.commit_group;" ::: "memory");
}
template <int N>
__device__ __forceinline__ void cp_wait() {
    asm volatile("cp.async.wait_group %0;" :: "n"(N) : "memory");
}
__device__ __forceinline__ void ldsm_x4(uint32_t* r, uint32_t a) {
    asm volatile("ldmatrix.sync.aligned.m8n8.x4.shared.b16 {%0,%1,%2,%3}, [%4];"
        : "=r"(r[0]), "=r"(r[1]), "=r"(r[2]), "=r"(r[3]) : "r"(a));
}
__device__ __forceinline__ void mma16816(float* d, const uint32_t* a, const uint32_t* b) {
    asm volatile("mma.sync.aligned.m16n8k16.row.col.f32.f16.f16.f32 "
        "{%0,%1,%2,%3}, {%4,%5,%6,%7}, {%8,%9}, {%0,%1,%2,%3};"
        : "+f"(d[0]), "+f"(d[1]), "+f"(d[2]), "+f"(d[3])
        : "r"(a[0]), "r"(a[1]), "r"(a[2]), "r"(a[3]), "r"(b[0]), "r"(b[1]));
}

__device__ __forceinline__ float block_sum1(float a, float* red) {
    #pragma unroll
    for (int off = 16; off > 0; off >>= 1) a += __shfl_xor_sync(0xffffffffu, a, off);
    int t = threadIdx.x;
    if ((t & 31) == 0) red[t >> 5] = a;
    __syncthreads();
    if (t == 0) {
        float s = 0.f;
        #pragma unroll
        for (int i = 0; i < 8; i++) s += red[i];
        red[8] = s;
    }
    __syncthreads();
    return red[8];
}

__device__ __forceinline__ void block_sum2(float& a, float& b, float* red) {
    #pragma unroll
    for (int off = 16; off > 0; off >>= 1) {
        a += __shfl_xor_sync(0xffffffffu, a, off);
        b += __shfl_xor_sync(0xffffffffu, b, off);
    }
    int t = threadIdx.x;
    if ((t & 31) == 0) { red[t >> 5] = a; red[8 + (t >> 5)] = b; }
    __syncthreads();
    if (t == 0) {
        float sa = 0.f, sb = 0.f;
        #pragma unroll
        for (int i = 0; i < 8; i++) { sa += red[i]; sb += red[8 + i]; }
        red[16] = sa; red[17] = sb;
    }
    __syncthreads();
    a = red[16]; b = red[17];
}

__device__ __forceinline__ void split_write_h(
    __half* __restrict__ oh, __half* __restrict__ ol, size_t idx, float v)
{
    __half hv = __float2half_rn(v);
    oh[idx] = hv;
    ol[idx] = __float2half_rn(v - __half2float(hv));
}

__global__ __launch_bounds__(256) void embed_kernel(
    const int* __restrict__ ids, const float* __restrict__ we,
    const float* __restrict__ te, const float* __restrict__ pe,
    const float* __restrict__ lw, const float* __restrict__ lb,
    float* __restrict__ x, __half* __restrict__ xh, __half* __restrict__ xl)
{
    __shared__ float buf[HID];
    __shared__ float red[32];
    int row = blockIdx.x, t = threadIdx.x;
    int l = row & (LSEQ - 1);
    int id = ids[row];
    float s = 0.f;
    for (int j = t; j < HID; j += 256) {
        float v = we[(size_t)id * HID + j] + te[j] + pe[(size_t)l * HID + j];
        buf[j] = v; s += v;
    }
    float mean = block_sum1(s, red) * (1.f / HID);
    float vs = 0.f;
    for (int j = t; j < HID; j += 256) { float d = buf[j] - mean; vs += d * d; }
    float var = block_sum1(vs, red) * (1.f / HID);
    float inv = 1.0f / sqrtf(var + 1e-12f);
    for (int j = t; j < HID; j += 256) {
        float v = (buf[j] - mean) * inv * lw[j] + lb[j];
        x[(size_t)row * HID + j] = v;
        split_write_h(xh, xl, (size_t)row * HID + j, v);
    }
}

__global__ __launch_bounds__(256) void ln_res_kernel(
    const float* __restrict__ resid, const float* __restrict__ y,
    const float* __restrict__ bias, const float* __restrict__ w,
    const float* __restrict__ bp, float* __restrict__ out,
    __half* __restrict__ oh, __half* __restrict__ ol)
{
    __shared__ float buf[HID];
    __shared__ float red[32];
    int row = blockIdx.x, t = threadIdx.x;
    float s = 0.f;
    for (int j = t; j < HID; j += 256) {
        float v = resid[(size_t)row * HID + j] + y[(size_t)row * HID + j];
        if (bias) v += bias[j];
        buf[j] = v; s += v;
    }
    float mean = block_sum1(s, red) * (1.f / HID);
    float vs = 0.f;
    for (int j = t; j < HID; j += 256) { float d = buf[j] - mean; vs += d * d; }
    float var = block_sum1(vs, red) * (1.f / HID);
    float inv = 1.0f / sqrtf(var + 1e-12f);
    for (int j = t; j < HID; j += 256) {
        float v = (buf[j] - mean) * inv * w[j] + bp[j];
        out[(size_t)row * HID + j] = v;
        if (oh) split_write_h(oh, ol, (size_t)row * HID + j, v);
    }
}

__global__ void tsplit_kernel(const float* __restrict__ W, __half* __restrict__ Th,
                              int K, int N, size_t tstride)
{
    __shared__ float tile[32][33];
    int layer = blockIdx.z;
    const float* Wp = W + (size_t)layer * K * N;
    __half* Tp = Th + (size_t)layer * tstride;
    int k0 = blockIdx.y * 32, n0 = blockIdx.x * 32;
    int tx = threadIdx.x, ty = threadIdx.y;
    #pragma unroll
    for (int j = 0; j < 4; j++)
        tile[ty + 8*j][tx] = Wp[(size_t)(k0 + ty + 8*j) * N + n0 + tx];
    __syncthreads();
    #pragma unroll
    for (int j = 0; j < 4; j++) {
        int n = n0 + ty + 8*j, k = k0 + tx;
        Tp[(size_t)n * K + k] = __float2half_rn(tile[tx][ty + 8*j]);
    }
}

#define BK 32
#define LDS 40
#define ARR_ELEM (128*LDS)
#define STAGE_ELEM (3*ARR_ELEM)
#define GEMM_SMEM (2*STAGE_ELEM*2)

__global__ __launch_bounds__(256) void gemm_f16x2(
    const __half* __restrict__ Ah, const __half* __restrict__ Al,
    const __half* __restrict__ Bh,
    int K, int N, int epi, const float* __restrict__ bias,
    float* __restrict__ C, float* __restrict__ Cq, float* __restrict__ Ck, float* __restrict__ Cv,
    __half* __restrict__ H, __half* __restrict__ L)
{
    extern __shared__ __half smem[];
    uint32_t smb = smem_u32(smem);
    int tid = threadIdx.x, lane = tid & 31, wid = tid >> 5;
    int bx = blockIdx.x, by = blockIdx.y;
    int wy = wid >> 2, wx = wid & 3;
    int m0 = wy * 64, n0 = wx * 32;

    const char* gsrc[3] = {
        (const char*)(Ah + (size_t)(by * 128) * K),
        (const char*)(Al + (size_t)(by * 128) * K),
        (const char*)(Bh + (size_t)(bx * 128) * K)
    };

    int r0 = tid >> 2, cq = tid & 3;
    int r1 = r0 + 64;

    float acc[4][4][4];
    #pragma unroll
    for (int mt = 0; mt < 4; mt++)
        #pragma unroll
        for (int nt = 0; nt < 4; nt++)
            #pragma unroll
            for (int e = 0; e < 4; e++) acc[mt][nt][e] = 0.f;

    int NKB = K / BK;

    {
        #pragma unroll
        for (int m = 0; m < 3; m++) {
            uint32_t sb = smb + (uint32_t)(m * ARR_ELEM) * 2;
            cp_async16(sb + (uint32_t)(r0 * LDS + cq * 8) * 2, gsrc[m] + (size_t)r0 * K * 2 + cq * 16);
            cp_async16(sb + (uint32_t)(r1 * LDS + cq * 8) * 2, gsrc[m] + (size_t)r1 * K * 2 + cq * 16);
        }
        cp_commit();
    }

    int aj = lane >> 3;
    int arow = ((aj & 1) << 3) + (lane & 7);
    int acol = (aj >> 1) << 3;
    int brow = ((aj >> 1) << 3) + (lane & 7);
    int bcol = (aj & 1) << 3;

    for (int kb = 0; kb < NKB; kb++) {
        int s = kb & 1;
        if (kb + 1 < NKB) {
            int s2 = s ^ 1;
            int koff = (kb + 1) * (BK * 2);
            #pragma unroll
            for (int m = 0; m < 3; m++) {
                uint32_t sb = smb + (uint32_t)(s2 * STAGE_ELEM + m * ARR_ELEM) * 2;
                cp_async16(sb + (uint32_t)(r0 * LDS + cq * 8) * 2, gsrc[m] + (size_t)r0 * K * 2 + koff + cq * 16);
                cp_async16(sb + (uint32_t)(r1 * LDS + cq * 8) * 2, gsrc[m] + (size_t)r1 * K * 2 + koff + cq * 16);
            }
            cp_commit();
            cp_wait<1>();
        } else {
            cp_wait<0>();
        }
        __syncthreads();

        uint32_t stb = smb + (uint32_t)(s * STAGE_ELEM) * 2;
        uint32_t aAh = stb;
        uint32_t aAl = stb + (uint32_t)ARR_ELEM * 2;
        uint32_t aBh = stb + (uint32_t)(2 * ARR_ELEM) * 2;

        #pragma unroll
        for (int ks = 0; ks < 2; ks++) {
            int kc = ks * 16;
            uint32_t ah[4][4], al[4][4];
            #pragma unroll
            for (int mt = 0; mt < 4; mt++) {
                uint32_t off = (uint32_t)((m0 + mt * 16 + arow) * LDS + kc + acol) * 2;
                ldsm_x4(ah[mt], aAh + off);
                ldsm_x4(al[mt], aAl + off);
            }
            #pragma unroll
            for (int p = 0; p < 2; p++) {
                uint32_t boff = (uint32_t)((n0 + p * 16 + brow) * LDS + kc + bcol) * 2;
                uint32_t b4[4];
                ldsm_x4(b4, aBh + boff);
                #pragma unroll
                for (int sub = 0; sub < 2; sub++) {
                    int nt = p * 2 + sub;
                    #pragma unroll
                    for (int mt = 0; mt < 4; mt++) {
                        mma16816(acc[mt][nt], ah[mt], b4 + sub * 2);
                        mma16816(acc[mt][nt], al[mt], b4 + sub * 2);
                    }
                }
            }
        }
        __syncthreads();
    }

    int gm0 = by * 128 + m0;
    int gn0 = bx * 128 + n0;
    #pragma unroll
    for (int mt = 0; mt < 4; mt++) {
        #pragma unroll
        for (int nt = 0; nt < 4; nt++) {
            int row0 = gm0 + mt * 16 + (lane >> 2);
            int col0 = gn0 + nt * 8 + (lane & 3) * 2;
            if (epi == 2) {
                #pragma unroll
                for (int half = 0; half < 2; half++) {
                    int row = row0 + half * 8;
                    float v0 = acc[mt][nt][half * 2 + 0] + bias[col0];
                    float v1 = acc[mt][nt][half * 2 + 1] + bias[col0 + 1];
                    v0 = 0.5f * v0 * (1.0f + erff(v0 * 0.70710678118654752f));
                    v1 = 0.5f * v1 * (1.0f + erff(v1 * 0.70710678118654752f));
                    __half h0 = __float2half_rn(v0);
                    __half h1 = __float2half_rn(v1);
                    *(__half2*)(H + (size_t)row * N + col0) = __half2(h0, h1);
                    *(__half2*)(L + (size_t)row * N + col0) =
                        __half2(__float2half_rn(v0 - __half2float(h0)),
                                __float2half_rn(v1 - __half2float(h1)));
                }
            } else {
                #pragma unroll
                for (int e = 0; e < 4; e++) {
                    int row = row0 + ((e >> 1) << 3);
                    int col = col0 + (e & 1);
                    float v = acc[mt][nt][e];
                    if (epi == 1) {
                        float sv = v / (1.0f + expf(-v));
                        int m = col / HID, cc = col - m * HID;
                        float* dst = (m == 0) ? Cq : (m == 1) ? Ck : Cv;
                        int b_ = row >> 9, l = row & (LSEQ - 1);
                        int h = cc >> 6, d = cc & 63;
                        dst[(size_t)((b_ * NH + h) * LSEQ + l) * DH + d] = sv;
                    } else {
                        C[(size_t)row * N + col] = v;
                    }
                }
            }
        }
    }
}

__global__ __launch_bounds__(256) void gates_kernel(
    const float* __restrict__ x,
    const float* __restrict__ fdw, const float* __restrict__ sdw,
    const float* __restrict__ fgw, const float* __restrict__ sgw,
    const float* __restrict__ fdb, const float* __restrict__ sdb,
    float* __restrict__ fd, float* __restrict__ sd,
    float* __restrict__ fg, float* __restrict__ sg)
{
    __shared__ float xs[64][68];
    __shared__ float ws[64][48];
    int t = threadIdx.x;
    int blk = blockIdx.x;
    int r = t >> 2, g = t & 3;
    float acc[12];
    #pragma unroll
    for (int j = 0; j < 12; j++) acc[j] = 0.f;

    for (int kt = 0; kt < HID; kt += 64) {
        #pragma unroll
        for (int u = 0; u < 4; u++) {
            int idx = u * 256 + t;
            int xr = idx >> 4, xq = idx & 15;
            float4 xv = *(const float4*)(x + (size_t)(blk * 64 + xr) * HID + kt + xq * 4);
            xs[xr][xq * 4 + 0] = xv.x; xs[xr][xq * 4 + 1] = xv.y;
            xs[xr][xq * 4 + 2] = xv.z; xs[xr][xq * 4 + 3] = xv.w;
        }
        #pragma unroll
        for (int u = 0; u < 12; u++) {
            int idx = u * 256 + t;
            int wk = idx / 48, wj = idx % 48;
            int m = wj / 12, jj = wj % 12;
            const float* W = (m == 0) ? fdw : (m == 1) ? sdw : (m == 2) ? fgw : sgw;
            ws[wk][wj] = W[(size_t)(kt + wk) * NH + jj];
        }
        __syncthreads();
        for (int kk = 0; kk < 64; kk++) {
            float xv = xs[r][kk];
            #pragma unroll
            for (int j = 0; j < 12; j++) acc[j] += xv * ws[kk][g * 12 + j];
        }
        __syncthreads();
    }
    int token = blk * 64 + r;
    int b = token >> 9, l = token & (LSEQ - 1);
    float* dst = (g == 0) ? fd : (g == 1) ? sd : (g == 2) ? fg : sg;
    #pragma unroll
    for (int j = 0; j < 12; j++) {
        float vv = acc[j];
        if (g == 0) vv += fdb[j];
        else if (g == 1) vv += sdb[j];
        vv = 1.0f / (1.0f + expf(-vv));
        dst[(size_t)(b * NH + j) * LSEQ + l] = vv;
    }
}

__global__ __launch_bounds__(256) void cmean_kernel(
    const float* __restrict__ fd, const float* __restrict__ sd,
    float* __restrict__ fdm, float* __restrict__ sdm)
{
    __shared__ float red[32];
    int bid = blockIdx.x;
    int bh = bid >> 1, c = bid & 1;
    int t = threadIdx.x;
    float a = fd[(size_t)bh * LSEQ + c * 256 + t];
    float b = sd[(size_t)bh * LSEQ + c * 256 + t];
    block_sum2(a, b, red);
    if (t == 0) { fdm[bid] = a * (1.f / 256.f); sdm[bid] = b * (1.f / 256.f); }
}

#define SPAD 257
#define QPAD 66
#define DELTA_SMEM_BYTES ((4*4096 + 2*16896 + 40) * 4)

__global__ __launch_bounds__(256, 1) void delta_kernel(
    const float* __restrict__ q, const float* __restrict__ k, const float* __restrict__ v,
    const float* __restrict__ fg, const float* __restrict__ sg,
    const float* __restrict__ fdm, const float* __restrict__ sdm,
    float* __restrict__ o)
{
    extern __shared__ float smf[];
    float* Sf = smf;
    float* Ss = Sf + 4096;
    float* G  = Ss + 4096;
    float* A  = G + 4096;
    float* T0 = A + 4096;
    float* T1 = T0 + 16896;
    float* red = T1 + 16896;

    int t = threadIdx.x;
    int bh = blockIdx.x;
    int b = bh / NH, h = bh % NH;
    int d = t >> 2, g = t & 3, e0 = g * 16;

    #pragma unroll
    for (int j = 0; j < 16; j++) { Sf[d * 64 + e0 + j] = 0.f; Ss[d * 64 + e0 + j] = 0.f; }
    __syncthreads();

    const float* qb = q + (size_t)bh * LSEQ * DH;
    const float* kb = k + (size_t)bh * LSEQ * DH;
    const float* vb = v + (size_t)bh * LSEQ * DH;

    for (int c = 0; c < 2; c++) {
        int c0 = c * 256;
        float df = powf(fdm[bh * 2 + c], 256.0f);
        float ds = powf(sdm[bh * 2 + c], 256.0f);

        float pf = 0.f, ps = 0.f;
        #pragma unroll
        for (int j = 0; j < 16; j++) {
            int idx = d * 64 + e0 + j;
            float a = Sf[idx] * df; Sf[idx] = a; pf += a * a;
            float bb = Ss[idx] * ds; Ss[idx] = bb; ps += bb * bb;
        }
        block_sum2(pf, ps, red);
        float rf = 1.0f / (sqrtf(pf) + 1e-8f);
        float rs = 1.0f / (sqrtf(ps) + 1e-8f);

        #pragma unroll
        for (int u = 0; u < 16; u++) {
            int idx4 = u * 256 + t;
            int r = idx4 >> 4, e4 = (idx4 & 15) * 4;
            float4 kv = *(const float4*)(kb + (size_t)(c0 + r) * DH + e4);
            T0[(e4 + 0) * SPAD + r] = kv.x; T0[(e4 + 1) * SPAD + r] = kv.y;
            T0[(e4 + 2) * SPAD + r] = kv.z; T0[(e4 + 3) * SPAD + r] = kv.w;
            float4 vv = *(const float4*)(vb + (size_t)(c0 + r) * DH + e4);
            T1[(e4 + 0) * SPAD + r] = vv.x; T1[(e4 + 1) * SPAD + r] = vv.y;
            T1[(e4 + 2) * SPAD + r] = vv.z; T1[(e4 + 3) * SPAD + r] = vv.w;
        }
        __syncthreads();

        {
            float accG[16], accA[16];
            #pragma unroll
            for (int j = 0; j < 16; j++) { accG[j] = 0.f; accA[j] = 0.f; }
            for (int r = 0; r < 256; r++) {
                float kd = T0[d * SPAD + r];
                #pragma unroll
                for (int j = 0; j < 16; j++) {
                    accG[j] += kd * T0[(e0 + j) * SPAD + r];
                    accA[j] += kd * T1[(e0 + j) * SPAD + r];
                }
            }
            #pragma unroll
            for (int j = 0; j < 16; j++) { G[d * 64 + e0 + j] = accG[j]; A[d * 64 + e0 + j] = accA[j]; }
        }
        __syncthreads();

        #pragma unroll
        for (int u = 0; u < 16; u++) {
            int idx4 = u * 256 + t;
            int r = idx4 >> 4, e4 = (idx4 & 15) * 4;
            float4 qv = *(const float4*)(qb + (size_t)(c0 + r) * DH + e4);
            T0[r * QPAD + e4 + 0] = qv.x; T0[r * QPAD + e4 + 1] = qv.y;
            T0[r * QPAD + e4 + 2] = qv.z; T0[r * QPAD + e4 + 3] = qv.w;
        }
        __syncthreads();

        {
            float of[16], os[16];
            #pragma unroll
            for (int j = 0; j < 16; j++) { of[j] = 0.f; os[j] = 0.f; }
            for (int kk = 0; kk < 64; kk++) {
                float qv = T0[d * QPAD + kk];
                #pragma unroll
                for (int j = 0; j < 16; j++) {
                    of[j] += qv * Sf[kk * 64 + e0 + j];
                    os[j] += qv * Ss[kk * 64 + e0 + j];
                }
            }
            float fgv = fg[(size_t)bh * LSEQ + c0 + d];
            float sgv = sg[(size_t)bh * LSEQ + c0 + d];
            float* orow = o + (size_t)(b * LSEQ + c0 + d) * HID + h * DH + e0;
            #pragma unroll
            for (int j = 0; j < 16; j++)
                orow[j] = 0.6f * fgv * of[j] * rf + 0.4f * sgv * os[j] * rs;
        }

        {
            float tf[16], ts[16];
            #pragma unroll
            for (int j = 0; j < 16; j++) { tf[j] = 0.f; ts[j] = 0.f; }
            for (int kk = 0; kk < 64; kk++) {
                float gv = G[d * 64 + kk];
                #pragma unroll
                for (int j = 0; j < 16; j++) {
                    tf[j] += gv * Sf[kk * 64 + e0 + j];
                    ts[j] += gv * Ss[kk * 64 + e0 + j];
                }
            }
            __syncthreads();
            float nf = 0.f, ns = 0.f;
            #pragma unroll
            for (int j = 0; j < 16; j++) {
                int idx = d * 64 + e0 + j;
                float sv = Sf[idx] + A[idx] - tf[j] * rf;
                Sf[idx] = sv; nf += sv * sv;
                float sw = Ss[idx] + A[idx] - ts[j] * rs;
                Ss[idx] = sw; ns += sw * sw;
            }
            block_sum2(nf, ns, red);
            float qf = 1.0f / (sqrtf(nf) + 1e-8f);
            float qs = 1.0f / (sqrtf(ns) + 1e-8f);
            #pragma unroll
            for (int j = 0; j < 16; j++) {
                int idx = d * 64 + e0 + j;
                Sf[idx] *= qf; Ss[idx] *= qs;
            }
            __syncthreads();
        }
    }
}

__global__ __launch_bounds__(256) void rms_kernel(
    const float* __restrict__ o, const float* __restrict__ w,
    __half* __restrict__ oh, __half* __restrict__ ol)
{
    int warp = threadIdx.x >> 5, lane = threadIdx.x & 31;
    size_t row = (size_t)blockIdx.x * 8 + warp;
    const float2* p = (const float2*)(o + row * DH) + lane;
    float2 v = *p;
    float ss = v.x * v.x + v.y * v.y;
    #pragma unroll
    for (int off = 16; off > 0; off >>= 1) ss += __shfl_xor_sync(0xffffffffu, ss, off);
    float inv = 1.0f / sqrtf(ss * (1.f / 64.f) + 1e-6f);
    float v0 = v.x * inv * w[lane * 2];
    float v1 = v.y * inv * w[lane * 2 + 1];
    __half h0 = __float2half_rn(v0);
    __half h1 = __float2half_rn(v1);
    ((__half2*)(oh + row * DH))[lane] = __half2(h0, h1);
    ((__half2*)(ol + row * DH))[lane] =
        __half2(__float2half_rn(v0 - __half2float(h0)),
                __float2half_rn(v1 - __half2float(h1)));
}

static float* symf(const void* sym) { void* p = nullptr; cudaGetSymbolAddress(&p, sym); return (float*)p; }
static __half* symh(const void* sym) { void* p = nullptr; cudaGetSymbolAddress(&p, sym); return (__half*)p; }

extern "C" void kernel_launch(void* const* d_in, const int* in_sizes, int n_in,
                              void* d_out, int out_size)
{
    const int*   ids = (const int*)  d_in[0];
    const float* we  = (const float*)d_in[1];
    const float* te  = (const float*)d_in[2];
    const float* pe  = (const float*)d_in[3];
    const float* elw = (const float*)d_in[4];
    const float* elb = (const float*)d_in[5];
    const float* qw  = (const float*)d_in[6];
    const float* kw  = (const float*)d_in[7];
    const float* vw  = (const float*)d_in[8];
    const float* fdw = (const float*)d_in[9];
    const float* fdb = (const float*)d_in[10];
    const float* sdw = (const float*)d_in[11];
    const float* sdb = (const float*)d_in[12];
    const float* fgw = (const float*)d_in[13];
    const float* sgw = (const float*)d_in[14];
    const float* onw = (const float*)d_in[15];
    const float* ow  = (const float*)d_in[16];
    const float* alw = (const float*)d_in[17];
    const float* alb = (const float*)d_in[18];
    const float* w1  = (const float*)d_in[19];
    const float* b1  = (const float*)d_in[20];
    const float* w2  = (const float*)d_in[21];
    const float* b2  = (const float*)d_in[22];
    const float* flw = (const float*)d_in[23];
    const float* flb = (const float*)d_in[24];
    float* out = (float*)d_out;

    float* px  = symf(g_x);  float* pq  = symf(g_q);  float* pk  = symf(g_k);
    float* pv  = symf(g_v);  float* po  = symf(g_o);  float* py  = symf(g_y);
    float* pfd = symf(g_fd); float* psd = symf(g_sd);
    float* pfg = symf(g_fg); float* psg = symf(g_sg);
    float* pfdm = symf(g_fdm); float* psdm = symf(g_sdm);
    __half* pwh = symh(g_wh);
    __half* pxh = symh(g_xh);  __half* pxl = symh(g_xl);
    __half* phh = pxh + (size_t)NTOK * HID;
    __half* phl = pxl + (size_t)NTOK * HID;

    static bool attr_done = false;
    if (!attr_done) {
        cudaFuncSetAttribute(delta_kernel, cudaFuncAttributeMaxDynamicSharedMemorySize, DELTA_SMEM_BYTES);
        cudaFuncSetAttribute(gemm_f16x2, cudaFuncAttributeMaxDynamicSharedMemorySize, GEMM_SMEM);
        attr_done = true;
    }

    dim3 tb(32, 8);
    tsplit_kernel<<<dim3(HID/32, HID/32, NLAY), tb>>>(qw, pwh,            HID, HID, WLAYER);
    tsplit_kernel<<<dim3(HID/32, HID/32, NLAY), tb>>>(kw, pwh + WQKV,     HID, HID, WLAYER);
    tsplit_kernel<<<dim3(HID/32, HID/32, NLAY), tb>>>(vw, pwh + 2*WQKV,   HID, HID, WLAYER);
    tsplit_kernel<<<dim3(HID/32, HID/32, NLAY), tb>>>(ow, pwh + 3*WQKV,   HID, HID, WLAYER);
    tsplit_kernel<<<dim3(FFND/32, HID/32, NLAY), tb>>>(w1, pwh + 4*WQKV,        HID, FFND, WLAYER);
    tsplit_kernel<<<dim3(HID/32, FFND/32, NLAY), tb>>>(w2, pwh + 4*WQKV + WFFN, FFND, HID, WLAYER);

    embed_kernel<<<NTOK, 256>>>(ids, we, te, pe, elw, elb, px, pxh, pxl);

    dim3 gQKV(3*HID / 128, NTOK / 128);
    dim3 gO(HID / 128, NTOK / 128);
    dim3 gF1(FFND / 128, NTOK / 128);

    for (int i = 0; i < NLAY; i++) {
        size_t base = (size_t)i * WLAYER;

        gemm_f16x2<<<gQKV, 256, GEMM_SMEM>>>(pxh, pxl, pwh + base,
            HID, 3*HID, 1, nullptr, nullptr, pq, pk, pv, nullptr, nullptr);

        gates_kernel<<<NTOK / 64, 256>>>(px,
            fdw + (size_t)i * HID * NH, sdw + (size_t)i * HID * NH,
            fgw + (size_t)i * HID * NH, sgw + (size_t)i * HID * NH,
            fdb + (size_t)i * NH, sdb + (size_t)i * NH,
            pfd, psd, pfg, psg);

        cmean_kernel<<<BATCH * NH * 2, 256>>>(pfd, psd, pfdm, psdm);
        delta_kernel<<<BATCH * NH, 256, DELTA_SMEM_BYTES>>>(pq, pk, pv, pfg, psg, pfdm, psdm, po);
        rms_kernel<<<(NTOK * NH) / 8, 256>>>(po, onw + (size_t)i * DH, pxh, pxl);

        gemm_f16x2<<<gO, 256, GEMM_SMEM>>>(pxh, pxl, pwh + base + 3*WQKV,
            HID, HID, 0, nullptr, py, nullptr, nullptr, nullptr, nullptr, nullptr);

        ln_res_kernel<<<NTOK, 256>>>(px, py, nullptr,
            alw + (size_t)i * HID, alb + (size_t)i * HID, px, pxh, pxl);

        gemm_f16x2<<<gF1, 256, GEMM_SMEM>>>(pxh, pxl, pwh + base + 4*WQKV,
            HID, FFND, 2, b1 + (size_t)i * FFND, nullptr, nullptr, nullptr, nullptr, phh, phl);

        gemm_f16x2<<<gO, 256, GEMM_SMEM>>>(phh, phl, pwh + base + 4*WQKV + WFFN,
            FFND, HID, 0, nullptr, py, nullptr, nullptr, nullptr, nullptr, nullptr);

        float* dst = (i == NLAY - 1) ? out : px;
        __half* doh = (i == NLAY - 1) ? nullptr : pxh;
        __half* dol = (i == NLAY - 1) ? nullptr : pxl;
        ln_res_kernel<<<NTOK, 256>>>(px, py, b2 + (size_t)i * HID,
            flw + (size_t)i * HID, flb + (size_t)i * HID, dst, doh, dol);
    }
}

// round 12
// speedup vs baseline: 3.5081x; 1.2218x over previous
#include <cuda_runtime.h>
#include <cuda_fp16.h>
#include <cstdint>

#define NH 12
#define DH 64
#define HID 768
#define LSEQ 512
#define BATCH 16
#define NTOK (BATCH*LSEQ)
#define FFND 3072
#define NLAY 6

#define WQKV (HID*HID)
#define WFFN (HID*FFND)
#define WLAYER (4*WQKV + 2*WFFN)

__device__ float g_x [NTOK*HID];
__device__ float g_q [NTOK*HID];
__device__ float g_k [NTOK*HID];
__device__ float g_v [NTOK*HID];
__device__ float g_o [NTOK*HID];
__device__ float g_y [NTOK*HID];
__device__ float g_fd[BATCH*NH*LSEQ];
__device__ float g_sd[BATCH*NH*LSEQ];
__device__ float g_fg[BATCH*NH*LSEQ];
__device__ float g_sg[BATCH*NH*LSEQ];
__device__ float g_fdm[BATCH*NH*2];
__device__ float g_sdm[BATCH*NH*2];
__device__ __align__(16) __half g_wh[NLAY*WLAYER];
__device__ __align__(16) __half g_xh[NTOK*(HID+FFND)];

__device__ __forceinline__ uint32_t smem_u32(const void* p) {
    uint32_t a;
    asm("{ .reg .u64 t; cvta.to.shared.u64 t, %1; cvt.u32.u64 %0, t; }" : "=r"(a) : "l"(p));
    return a;
}
__device__ __forceinline__ void cp_async16(uint32_t saddr, const void* gaddr) {
    asm volatile("cp.async.cg.shared.global [%0], [%1], 16;" :: "r"(saddr), "l"(gaddr) : "memory");
}
__device__ __forceinline__ void cp_commit() {
    asm volatile("cp.async.commit_group;" ::: "memory");
}
template <int N>
__device__ __forceinline__ void cp_wait() {
    asm volatile("cp.async.wait_group %0;" :: "n"(N) : "memory");
}
__device__ __forceinline__ void ldsm_x4(uint32_t* r, uint32_t a) {
    asm volatile("ldmatrix.sync.aligned.m8n8.x4.shared.b16 {%0,%1,%2,%3}, [%4];"
        : "=r"(r[0]), "=r"(r[1]), "=r"(r[2]), "=r"(r[3]) : "r"(a));
}
__device__ __forceinline__ void mma16816(float* d, const uint32_t* a, const uint32_t* b) {
    asm volatile("mma.sync.aligned.m16n8k16.row.col.f32.f16.f16.f32 "
        "{%0,%1,%2,%3}, {%4,%5,%6,%7}, {%8,%9}, {%0,%1,%2,%3};"
        : "+f"(d[0]), "+f"(d[1]), "+f"(d[2]), "+f"(d[3])
        : "r"(a[0]), "r"(a[1]), "r"(a[2]), "r"(a[3]), "r"(b[0]), "r"(b[1]));
}

__device__ __forceinline__ float block_sum1(float a, float* red) {
    #pragma unroll
    for (int off = 16; off > 0; off >>= 1) a += __shfl_xor_sync(0xffffffffu, a, off);
    int t = threadIdx.x;
    if ((t & 31) == 0) red[t >> 5] = a;
    __syncthreads();
    if (t == 0) {
        float s = 0.f;
        #pragma unroll
        for (int i = 0; i < 8; i++) s += red[i];
        red[8] = s;
    }
    __syncthreads();
    return red[8];
}

__device__ __forceinline__ void block_sum2(float& a, float& b, float* red) {
    #pragma unroll
    for (int off = 16; off > 0; off >>= 1) {
        a += __shfl_xor_sync(0xffffffffu, a, off);
        b += __shfl_xor_sync(0xffffffffu, b, off);
    }
    int t = threadIdx.x;
    if ((t & 31) == 0) { red[t >> 5] = a; red[8 + (t >> 5)] = b; }
    __syncthreads();
    if (t == 0) {
        float sa = 0.f, sb = 0.f;
        #pragma unroll
        for (int i = 0; i < 8; i++) { sa += red[i]; sb += red[8 + i]; }
        red[16] = sa; red[17] = sb;
    }
    __syncthreads();
    a = red[16]; b = red[17];
}

/* ---------------- embedding + LN (+ fp16 store) ---------------- */
__global__ __launch_bounds__(256) void embed_kernel(
    const int* __restrict__ ids, const float* __restrict__ we,
    const float* __restrict__ te, const float* __restrict__ pe,
    const float* __restrict__ lw, const float* __restrict__ lb,
    float* __restrict__ x, __half* __restrict__ xh)
{
    __shared__ float buf[HID];
    __shared__ float red[32];
    int row = blockIdx.x, t = threadIdx.x;
    int l = row & (LSEQ - 1);
    int id = ids[row];
    float s = 0.f;
    for (int j = t; j < HID; j += 256) {
        float v = we[(size_t)id * HID + j] + te[j] + pe[(size_t)l * HID + j];
        buf[j] = v; s += v;
    }
    float mean = block_sum1(s, red) * (1.f / HID);
    float vs = 0.f;
    for (int j = t; j < HID; j += 256) { float d = buf[j] - mean; vs += d * d; }
    float var = block_sum1(vs, red) * (1.f / HID);
    float inv = 1.0f / sqrtf(var + 1e-12f);
    for (int j = t; j < HID; j += 256) {
        float v = (buf[j] - mean) * inv * lw[j] + lb[j];
        x[(size_t)row * HID + j] = v;
        xh[(size_t)row * HID + j] = __float2half_rn(v);
    }
}

/* ---------------- residual + optional bias + LN (+ optional fp16 store) ---------------- */
__global__ __launch_bounds__(256) void ln_res_kernel(
    const float* __restrict__ resid, const float* __restrict__ y,
    const float* __restrict__ bias, const float* __restrict__ w,
    const float* __restrict__ bp, float* __restrict__ out,
    __half* __restrict__ oh)
{
    __shared__ float buf[HID];
    __shared__ float red[32];
    int row = blockIdx.x, t = threadIdx.x;
    float s = 0.f;
    for (int j = t; j < HID; j += 256) {
        float v = resid[(size_t)row * HID + j] + y[(size_t)row * HID + j];
        if (bias) v += bias[j];
        buf[j] = v; s += v;
    }
    float mean = block_sum1(s, red) * (1.f / HID);
    float vs = 0.f;
    for (int j = t; j < HID; j += 256) { float d = buf[j] - mean; vs += d * d; }
    float var = block_sum1(vs, red) * (1.f / HID);
    float inv = 1.0f / sqrtf(var + 1e-12f);
    for (int j = t; j < HID; j += 256) {
        float v = (buf[j] - mean) * inv * w[j] + bp[j];
        out[(size_t)row * HID + j] = v;
        if (oh) oh[(size_t)row * HID + j] = __float2half_rn(v);
    }
}

/* ---------------- weight transpose: W[NLAY,K,N] -> Th[NLAY(strided),N,K] fp16 ---------------- */
__global__ void tsplit_kernel(const float* __restrict__ W, __half* __restrict__ Th,
                              int K, int N, size_t tstride)
{
    __shared__ float tile[32][33];
    int layer = blockIdx.z;
    const float* Wp = W + (size_t)layer * K * N;
    __half* Tp = Th + (size_t)layer * tstride;
    int k0 = blockIdx.y * 32, n0 = blockIdx.x * 32;
    int tx = threadIdx.x, ty = threadIdx.y;
    #pragma unroll
    for (int j = 0; j < 4; j++)
        tile[ty + 8*j][tx] = Wp[(size_t)(k0 + ty + 8*j) * N + n0 + tx];
    __syncthreads();
    #pragma unroll
    for (int j = 0; j < 4; j++) {
        int n = n0 + ty + 8*j, k = k0 + tx;
        Tp[(size_t)n * K + k] = __float2half_rn(tile[tx][ty + 8*j]);
    }
}

/* ---------------- fp16 warp-MMA GEMM: C[M,N] = A[M,K] @ Bt[N,K]^T ----------------
   epi: 0 plain fp32 C; 1 silu + scatter to Cq/Ck/Cv (N=2304 packed QKV);
   2 gelu(v+bias) -> fp16 H. */
#define BK 32
#define LDS 40
#define ARR_ELEM (128*LDS)
#define STAGE_ELEM (2*ARR_ELEM)
#define GEMM_SMEM (2*STAGE_ELEM*2)   /* 40960 bytes */

__global__ __launch_bounds__(256) void gemm_f16(
    const __half* __restrict__ Ah, const __half* __restrict__ Bh,
    int K, int N, int epi, const float* __restrict__ bias,
    float* __restrict__ C, float* __restrict__ Cq, float* __restrict__ Ck, float* __restrict__ Cv,
    __half* __restrict__ H)
{
    extern __shared__ __half smem[];
    uint32_t smb = smem_u32(smem);
    int tid = threadIdx.x, lane = tid & 31, wid = tid >> 5;
    int bx = blockIdx.x, by = blockIdx.y;
    int wy = wid >> 2, wx = wid & 3;
    int m0 = wy * 64, n0 = wx * 32;

    const char* gsrc[2] = {
        (const char*)(Ah + (size_t)(by * 128) * K),
        (const char*)(Bh + (size_t)(bx * 128) * K)
    };

    int r0 = tid >> 2, cq = tid & 3;
    int r1 = r0 + 64;

    float acc[4][4][4];
    #pragma unroll
    for (int mt = 0; mt < 4; mt++)
        #pragma unroll
        for (int nt = 0; nt < 4; nt++)
            #pragma unroll
            for (int e = 0; e < 4; e++) acc[mt][nt][e] = 0.f;

    int NKB = K / BK;

    {
        #pragma unroll
        for (int m = 0; m < 2; m++) {
            uint32_t sb = smb + (uint32_t)(m * ARR_ELEM) * 2;
            cp_async16(sb + (uint32_t)(r0 * LDS + cq * 8) * 2, gsrc[m] + (size_t)r0 * K * 2 + cq * 16);
            cp_async16(sb + (uint32_t)(r1 * LDS + cq * 8) * 2, gsrc[m] + (size_t)r1 * K * 2 + cq * 16);
        }
        cp_commit();
    }

    int aj = lane >> 3;
    int arow = ((aj & 1) << 3) + (lane & 7);
    int acol = (aj >> 1) << 3;
    int brow = ((aj >> 1) << 3) + (lane & 7);
    int bcol = (aj & 1) << 3;

    for (int kb = 0; kb < NKB; kb++) {
        int s = kb & 1;
        if (kb + 1 < NKB) {
            int s2 = s ^ 1;
            int koff = (kb + 1) * (BK * 2);
            #pragma unroll
            for (int m = 0; m < 2; m++) {
                uint32_t sb = smb + (uint32_t)(s2 * STAGE_ELEM + m * ARR_ELEM) * 2;
                cp_async16(sb + (uint32_t)(r0 * LDS + cq * 8) * 2, gsrc[m] + (size_t)r0 * K * 2 + koff + cq * 16);
                cp_async16(sb + (uint32_t)(r1 * LDS + cq * 8) * 2, gsrc[m] + (size_t)r1 * K * 2 + koff + cq * 16);
            }
            cp_commit();
            cp_wait<1>();
        } else {
            cp_wait<0>();
        }
        __syncthreads();

        uint32_t stb = smb + (uint32_t)(s * STAGE_ELEM) * 2;
        uint32_t aAh = stb;
        uint32_t aBh = stb + (uint32_t)ARR_ELEM * 2;

        #pragma unroll
        for (int ks = 0; ks < 2; ks++) {
            int kc = ks * 16;
            uint32_t ah[4][4];
            #pragma unroll
            for (int mt = 0; mt < 4; mt++) {
                uint32_t off = (uint32_t)((m0 + mt * 16 + arow) * LDS + kc + acol) * 2;
                ldsm_x4(ah[mt], aAh + off);
            }
            #pragma unroll
            for (int p = 0; p < 2; p++) {
                uint32_t boff = (uint32_t)((n0 + p * 16 + brow) * LDS + kc + bcol) * 2;
                uint32_t b4[4];
                ldsm_x4(b4, aBh + boff);
                #pragma unroll
                for (int sub = 0; sub < 2; sub++) {
                    int nt = p * 2 + sub;
                    #pragma unroll
                    for (int mt = 0; mt < 4; mt++)
                        mma16816(acc[mt][nt], ah[mt], b4 + sub * 2);
                }
            }
        }
        __syncthreads();
    }

    int gm0 = by * 128 + m0;
    int gn0 = bx * 128 + n0;
    #pragma unroll
    for (int mt = 0; mt < 4; mt++) {
        #pragma unroll
        for (int nt = 0; nt < 4; nt++) {
            int row0 = gm0 + mt * 16 + (lane >> 2);
            int col0 = gn0 + nt * 8 + (lane & 3) * 2;
            if (epi == 2) {
                #pragma unroll
                for (int half = 0; half < 2; half++) {
                    int row = row0 + half * 8;
                    float v0 = acc[mt][nt][half * 2 + 0] + bias[col0];
                    float v1 = acc[mt][nt][half * 2 + 1] + bias[col0 + 1];
                    v0 = 0.5f * v0 * (1.0f + erff(v0 * 0.70710678118654752f));
                    v1 = 0.5f * v1 * (1.0f + erff(v1 * 0.70710678118654752f));
                    *(__half2*)(H + (size_t)row * N + col0) =
                        __half2(__float2half_rn(v0), __float2half_rn(v1));
                }
            } else {
                #pragma unroll
                for (int e = 0; e < 4; e++) {
                    int row = row0 + ((e >> 1) << 3);
                    int col = col0 + (e & 1);
                    float v = acc[mt][nt][e];
                    if (epi == 1) {
                        float sv = v / (1.0f + expf(-v));
                        int m = col / HID, cc = col - m * HID;
                        float* dst = (m == 0) ? Cq : (m == 1) ? Ck : Cv;
                        int b_ = row >> 9, l = row & (LSEQ - 1);
                        int h = cc >> 6, d = cc & 63;
                        dst[(size_t)((b_ * NH + h) * LSEQ + l) * DH + d] = sv;
                    } else {
                        C[(size_t)row * N + col] = v;
                    }
                }
            }
        }
    }
}

/* ---------------- gates: 4x [8192,768]@[768,12] + sigmoid -> [b,h,l] ---------------- */
__global__ __launch_bounds__(256) void gates_kernel(
    const float* __restrict__ x,
    const float* __restrict__ fdw, const float* __restrict__ sdw,
    const float* __restrict__ fgw, const float* __restrict__ sgw,
    const float* __restrict__ fdb, const float* __restrict__ sdb,
    float* __restrict__ fd, float* __restrict__ sd,
    float* __restrict__ fg, float* __restrict__ sg)
{
    __shared__ float xs[64][68];
    __shared__ float ws[64][48];
    int t = threadIdx.x;
    int blk = blockIdx.x;
    int r = t >> 2, g = t & 3;
    float acc[12];
    #pragma unroll
    for (int j = 0; j < 12; j++) acc[j] = 0.f;

    for (int kt = 0; kt < HID; kt += 64) {
        #pragma unroll
        for (int u = 0; u < 4; u++) {
            int idx = u * 256 + t;
            int xr = idx >> 4, xq = idx & 15;
            float4 xv = *(const float4*)(x + (size_t)(blk * 64 + xr) * HID + kt + xq * 4);
            xs[xr][xq * 4 + 0] = xv.x; xs[xr][xq * 4 + 1] = xv.y;
            xs[xr][xq * 4 + 2] = xv.z; xs[xr][xq * 4 + 3] = xv.w;
        }
        #pragma unroll
        for (int u = 0; u < 12; u++) {
            int idx = u * 256 + t;
            int wk = idx / 48, wj = idx % 48;
            int m = wj / 12, jj = wj % 12;
            const float* W = (m == 0) ? fdw : (m == 1) ? sdw : (m == 2) ? fgw : sgw;
            ws[wk][wj] = W[(size_t)(kt + wk) * NH + jj];
        }
        __syncthreads();
        for (int kk = 0; kk < 64; kk++) {
            float xv = xs[r][kk];
            #pragma unroll
            for (int j = 0; j < 12; j++) acc[j] += xv * ws[kk][g * 12 + j];
        }
        __syncthreads();
    }
    int token = blk * 64 + r;
    int b = token >> 9, l = token & (LSEQ - 1);
    float* dst = (g == 0) ? fd : (g == 1) ? sd : (g == 2) ? fg : sg;
    #pragma unroll
    for (int j = 0; j < 12; j++) {
        float vv = acc[j];
        if (g == 0) vv += fdb[j];
        else if (g == 1) vv += sdb[j];
        vv = 1.0f / (1.0f + expf(-vv));
        dst[(size_t)(b * NH + j) * LSEQ + l] = vv;
    }
}

__global__ __launch_bounds__(256) void cmean_kernel(
    const float* __restrict__ fd, const float* __restrict__ sd,
    float* __restrict__ fdm, float* __restrict__ sdm)
{
    __shared__ float red[32];
    int bid = blockIdx.x;
    int bh = bid >> 1, c = bid & 1;
    int t = threadIdx.x;
    float a = fd[(size_t)bh * LSEQ + c * 256 + t];
    float b = sd[(size_t)bh * LSEQ + c * 256 + t];
    block_sum2(a, b, red);
    if (t == 0) { fdm[bid] = a * (1.f / 256.f); sdm[bid] = b * (1.f / 256.f); }
}

#define SPAD 257
#define QPAD 66
#define DELTA_SMEM_BYTES ((4*4096 + 2*16896 + 40) * 4)

__global__ __launch_bounds__(256, 1) void delta_kernel(
    const float* __restrict__ q, const float* __restrict__ k, const float* __restrict__ v,
    const float* __restrict__ fg, const float* __restrict__ sg,
    const float* __restrict__ fdm, const float* __restrict__ sdm,
    float* __restrict__ o)
{
    extern __shared__ float smf[];
    float* Sf = smf;
    float* Ss = Sf + 4096;
    float* G  = Ss + 4096;
    float* A  = G + 4096;
    float* T0 = A + 4096;
    float* T1 = T0 + 16896;
    float* red = T1 + 16896;

    int t = threadIdx.x;
    int bh = blockIdx.x;
    int b = bh / NH, h = bh % NH;
    int d = t >> 2, g = t & 3, e0 = g * 16;

    #pragma unroll
    for (int j = 0; j < 16; j++) { Sf[d * 64 + e0 + j] = 0.f; Ss[d * 64 + e0 + j] = 0.f; }
    __syncthreads();

    const float* qb = q + (size_t)bh * LSEQ * DH;
    const float* kb = k + (size_t)bh * LSEQ * DH;
    const float* vb = v + (size_t)bh * LSEQ * DH;

    for (int c = 0; c < 2; c++) {
        int c0 = c * 256;
        float df = powf(fdm[bh * 2 + c], 256.0f);
        float ds = powf(sdm[bh * 2 + c], 256.0f);

        float pf = 0.f, ps = 0.f;
        #pragma unroll
        for (int j = 0; j < 16; j++) {
            int idx = d * 64 + e0 + j;
            float a = Sf[idx] * df; Sf[idx] = a; pf += a * a;
            float bb = Ss[idx] * ds; Ss[idx] = bb; ps += bb * bb;
        }
        block_sum2(pf, ps, red);
        float rf = 1.0f / (sqrtf(pf) + 1e-8f);
        float rs = 1.0f / (sqrtf(ps) + 1e-8f);

        #pragma unroll
        for (int u = 0; u < 16; u++) {
            int idx4 = u * 256 + t;
            int r = idx4 >> 4, e4 = (idx4 & 15) * 4;
            float4 kv = *(const float4*)(kb + (size_t)(c0 + r) * DH + e4);
            T0[(e4 + 0) * SPAD + r] = kv.x; T0[(e4 + 1) * SPAD + r] = kv.y;
            T0[(e4 + 2) * SPAD + r] = kv.z; T0[(e4 + 3) * SPAD + r] = kv.w;
            float4 vv = *(const float4*)(vb + (size_t)(c0 + r) * DH + e4);
            T1[(e4 + 0) * SPAD + r] = vv.x; T1[(e4 + 1) * SPAD + r] = vv.y;
            T1[(e4 + 2) * SPAD + r] = vv.z; T1[(e4 + 3) * SPAD + r] = vv.w;
        }
        __syncthreads();

        {
            float accG[16], accA[16];
            #pragma unroll
            for (int j = 0; j < 16; j++) { accG[j] = 0.f; accA[j] = 0.f; }
            for (int r = 0; r < 256; r++) {
                float kd = T0[d * SPAD + r];
                #pragma unroll
                for (int j = 0; j < 16; j++) {
                    accG[j] += kd * T0[(e0 + j) * SPAD + r];
                    accA[j] += kd * T1[(e0 + j) * SPAD + r];
                }
            }
            #pragma unroll
            for (int j = 0; j < 16; j++) { G[d * 64 + e0 + j] = accG[j]; A[d * 64 + e0 + j] = accA[j]; }
        }
        __syncthreads();

        #pragma unroll
        for (int u = 0; u < 16; u++) {
            int idx4 = u * 256 + t;
            int r = idx4 >> 4, e4 = (idx4 & 15) * 4;
            float4 qv = *(const float4*)(qb + (size_t)(c0 + r) * DH + e4);
            T0[r * QPAD + e4 + 0] = qv.x; T0[r * QPAD + e4 + 1] = qv.y;
            T0[r * QPAD + e4 + 2] = qv.z; T0[r * QPAD + e4 + 3] = qv.w;
        }
        __syncthreads();

        {
            float of[16], os[16];
            #pragma unroll
            for (int j = 0; j < 16; j++) { of[j] = 0.f; os[j] = 0.f; }
            for (int kk = 0; kk < 64; kk++) {
                float qv = T0[d * QPAD + kk];
                #pragma unroll
                for (int j = 0; j < 16; j++) {
                    of[j] += qv * Sf[kk * 64 + e0 + j];
                    os[j] += qv * Ss[kk * 64 + e0 + j];
                }
            }
            float fgv = fg[(size_t)bh * LSEQ + c0 + d];
            float sgv = sg[(size_t)bh * LSEQ + c0 + d];
            float* orow = o + (size_t)(b * LSEQ + c0 + d) * HID + h * DH + e0;
            #pragma unroll
            for (int j = 0; j < 16; j++)
                orow[j] = 0.6f * fgv * of[j] * rf + 0.4f * sgv * os[j] * rs;
        }

        {
            float tf[16], ts[16];
            #pragma unroll
            for (int j = 0; j < 16; j++) { tf[j] = 0.f; ts[j] = 0.f; }
            for (int kk = 0; kk < 64; kk++) {
                float gv = G[d * 64 + kk];
                #pragma unroll
                for (int j = 0; j < 16; j++) {
                    tf[j] += gv * Sf[kk * 64 + e0 + j];
                    ts[j] += gv * Ss[kk * 64 + e0 + j];
                }
            }
            __syncthreads();
            float nf = 0.f, ns = 0.f;
            #pragma unroll
            for (int j = 0; j < 16; j++) {
                int idx = d * 64 + e0 + j;
                float sv = Sf[idx] + A[idx] - tf[j] * rf;
                Sf[idx] = sv; nf += sv * sv;
                float sw = Ss[idx] + A[idx] - ts[j] * rs;
                Ss[idx] = sw; ns += sw * sw;
            }
            block_sum2(nf, ns, red);
            float qf = 1.0f / (sqrtf(nf) + 1e-8f);
            float qs = 1.0f / (sqrtf(ns) + 1e-8f);
            #pragma unroll
            for (int j = 0; j < 16; j++) {
                int idx = d * 64 + e0 + j;
                Sf[idx] *= qf; Ss[idx] *= qs;
            }
            __syncthreads();
        }
    }
}

/* ---------------- per-(b,l,h) rms norm over d=64 -> fp16 ---------------- */
__global__ __launch_bounds__(256) void rms_kernel(
    const float* __restrict__ o, const float* __restrict__ w,
    __half* __restrict__ oh)
{
    int warp = threadIdx.x >> 5, lane = threadIdx.x & 31;
    size_t row = (size_t)blockIdx.x * 8 + warp;
    const float2* p = (const float2*)(o + row * DH) + lane;
    float2 v = *p;
    float ss = v.x * v.x + v.y * v.y;
    #pragma unroll
    for (int off = 16; off > 0; off >>= 1) ss += __shfl_xor_sync(0xffffffffu, ss, off);
    float inv = 1.0f / sqrtf(ss * (1.f / 64.f) + 1e-6f);
    float v0 = v.x * inv * w[lane * 2];
    float v1 = v.y * inv * w[lane * 2 + 1];
    ((__half2*)(oh + row * DH))[lane] = __half2(__float2half_rn(v0), __float2half_rn(v1));
}

static float* symf(const void* sym) { void* p = nullptr; cudaGetSymbolAddress(&p, sym); return (float*)p; }
static __half* symh(const void* sym) { void* p = nullptr; cudaGetSymbolAddress(&p, sym); return (__half*)p; }

extern "C" void kernel_launch(void* const* d_in, const int* in_sizes, int n_in,
                              void* d_out, int out_size)
{
    const int*   ids = (const int*)  d_in[0];
    const float* we  = (const float*)d_in[1];
    const float* te  = (const float*)d_in[2];
    const float* pe  = (const float*)d_in[3];
    const float* elw = (const float*)d_in[4];
    const float* elb = (const float*)d_in[5];
    const float* qw  = (const float*)d_in[6];
    const float* kw  = (const float*)d_in[7];
    const float* vw  = (const float*)d_in[8];
    const float* fdw = (const float*)d_in[9];
    const float* fdb = (const float*)d_in[10];
    const float* sdw = (const float*)d_in[11];
    const float* sdb = (const float*)d_in[12];
    const float* fgw = (const float*)d_in[13];
    const float* sgw = (const float*)d_in[14];
    const float* onw = (const float*)d_in[15];
    const float* ow  = (const float*)d_in[16];
    const float* alw = (const float*)d_in[17];
    const float* alb = (const float*)d_in[18];
    const float* w1  = (const float*)d_in[19];
    const float* b1  = (const float*)d_in[20];
    const float* w2  = (const float*)d_in[21];
    const float* b2  = (const float*)d_in[22];
    const float* flw = (const float*)d_in[23];
    const float* flb = (const float*)d_in[24];
    float* out = (float*)d_out;

    float* px  = symf(g_x);  float* pq  = symf(g_q);  float* pk  = symf(g_k);
    float* pv  = symf(g_v);  float* po  = symf(g_o);  float* py  = symf(g_y);
    float* pfd = symf(g_fd); float* psd = symf(g_sd);
    float* pfg = symf(g_fg); float* psg = symf(g_sg);
    float* pfdm = symf(g_fdm); float* psdm = symf(g_sdm);
    __half* pwh = symh(g_wh);
    __half* pxh = symh(g_xh);
    __half* phh = pxh + (size_t)NTOK * HID;

    static bool attr_done = false;
    if (!attr_done) {
        cudaFuncSetAttribute(delta_kernel, cudaFuncAttributeMaxDynamicSharedMemorySize, DELTA_SMEM_BYTES);
        cudaFuncSetAttribute(gemm_f16, cudaFuncAttributeMaxDynamicSharedMemorySize, GEMM_SMEM);
        attr_done = true;
    }

    dim3 tb(32, 8);
    tsplit_kernel<<<dim3(HID/32, HID/32, NLAY), tb>>>(qw, pwh,            HID, HID, WLAYER);
    tsplit_kernel<<<dim3(HID/32, HID/32, NLAY), tb>>>(kw, pwh + WQKV,     HID, HID, WLAYER);
    tsplit_kernel<<<dim3(HID/32, HID/32, NLAY), tb>>>(vw, pwh + 2*WQKV,   HID, HID, WLAYER);
    tsplit_kernel<<<dim3(HID/32, HID/32, NLAY), tb>>>(ow, pwh + 3*WQKV,   HID, HID, WLAYER);
    tsplit_kernel<<<dim3(FFND/32, HID/32, NLAY), tb>>>(w1, pwh + 4*WQKV,        HID, FFND, WLAYER);
    tsplit_kernel<<<dim3(HID/32, FFND/32, NLAY), tb>>>(w2, pwh + 4*WQKV + WFFN, FFND, HID, WLAYER);

    embed_kernel<<<NTOK, 256>>>(ids, we, te, pe, elw, elb, px, pxh);

    dim3 gQKV(3*HID / 128, NTOK / 128);
    dim3 gO(HID / 128, NTOK / 128);
    dim3 gF1(FFND / 128, NTOK / 128);

    for (int i = 0; i < NLAY; i++) {
        size_t base = (size_t)i * WLAYER;

        gemm_f16<<<gQKV, 256, GEMM_SMEM>>>(pxh, pwh + base,
            HID, 3*HID, 1, nullptr, nullptr, pq, pk, pv, nullptr);

        gates_kernel<<<NTOK / 64, 256>>>(px,
            fdw + (size_t)i * HID * NH, sdw + (size_t)i * HID * NH,
            fgw + (size_t)i * HID * NH, sgw + (size_t)i * HID * NH,
            fdb + (size_t)i * NH, sdb + (size_t)i * NH,
            pfd, psd, pfg, psg);

        cmean_kernel<<<BATCH * NH * 2, 256>>>(pfd, psd, pfdm, psdm);
        delta_kernel<<<BATCH * NH, 256, DELTA_SMEM_BYTES>>>(pq, pk, pv, pfg, psg, pfdm, psdm, po);
        rms_kernel<<<(NTOK * NH) / 8, 256>>>(po, onw + (size_t)i * DH, pxh);

        gemm_f16<<<gO, 256, GEMM_SMEM>>>(pxh, pwh + base + 3*WQKV,
            HID, HID, 0, nullptr, py, nullptr, nullptr, nullptr, nullptr);

        ln_res_kernel<<<NTOK, 256>>>(px, py, nullptr,
            alw + (size_t)i * HID, alb + (size_t)i * HID, px, pxh);

        gemm_f16<<<gF1, 256, GEMM_SMEM>>>(pxh, pwh + base + 4*WQKV,
            HID, FFND, 2, b1 + (size_t)i * FFND, nullptr, nullptr, nullptr, nullptr, phh);

        gemm_f16<<<gO, 256, GEMM_SMEM>>>(phh, pwh + base + 4*WQKV + WFFN,
            FFND, HID, 0, nullptr, py, nullptr, nullptr, nullptr, nullptr);

        float* dst = (i == NLAY - 1) ? out : px;
        __half* doh = (i == NLAY - 1) ? nullptr : pxh;
        ln_res_kernel<<<NTOK, 256>>>(px, py, b2 + (size_t)i * HID,
            flw + (size_t)i * HID, flb + (size_t)i * HID, dst, doh);
    }
}

// round 13
// speedup vs baseline: 3.8565x; 1.0993x over previous
#include <cuda_runtime.h>
#include <cuda_fp16.h>
#include <cstdint>

#define NH 12
#define DH 64
#define HID 768
#define LSEQ 512
#define BATCH 16
#define NTOK (BATCH*LSEQ)
#define FFND 3072
#define NLAY 6

#define WQKV (HID*HID)
#define WFFN (HID*FFND)
#define WLAYER (4*WQKV + 2*WFFN)

__device__ float g_x [NTOK*HID];
__device__ float g_q [NTOK*HID];
__device__ float g_k [NTOK*HID];
__device__ float g_v [NTOK*HID];
__device__ float g_o [NTOK*HID];
__device__ float g_y [NTOK*HID];
__device__ float g_fd[BATCH*NH*LSEQ];
__device__ float g_sd[BATCH*NH*LSEQ];
__device__ float g_fg[BATCH*NH*LSEQ];
__device__ float g_sg[BATCH*NH*LSEQ];
__device__ float g_fdm[BATCH*NH*2];
__device__ float g_sdm[BATCH*NH*2];
__device__ __align__(16) __half g_wh[NLAY*WLAYER];
__device__ __align__(16) __half g_xh[NTOK*(HID+FFND)];

__device__ __forceinline__ uint32_t smem_u32(const void* p) {
    uint32_t a;
    asm("{ .reg .u64 t; cvta.to.shared.u64 t, %1; cvt.u32.u64 %0, t; }" : "=r"(a) : "l"(p));
    return a;
}
__device__ __forceinline__ void cp_async16(uint32_t saddr, const void* gaddr) {
    asm volatile("cp.async.cg.shared.global [%0], [%1], 16;" :: "r"(saddr), "l"(gaddr) : "memory");
}
__device__ __forceinline__ void cp_commit() {
    asm volatile("cp.async.commit_group;" ::: "memory");
}
template <int N>
__device__ __forceinline__ void cp_wait() {
    asm volatile("cp.async.wait_group %0;" :: "n"(N) : "memory");
}
__device__ __forceinline__ void ldsm_x4(uint32_t* r, uint32_t a) {
    asm volatile("ldmatrix.sync.aligned.m8n8.x4.shared.b16 {%0,%1,%2,%3}, [%4];"
        : "=r"(r[0]), "=r"(r[1]), "=r"(r[2]), "=r"(r[3]) : "r"(a));
}
__device__ __forceinline__ void mma16816(float* d, const uint32_t* a, const uint32_t* b) {
    asm volatile("mma.sync.aligned.m16n8k16.row.col.f32.f16.f16.f32 "
        "{%0,%1,%2,%3}, {%4,%5,%6,%7}, {%8,%9}, {%0,%1,%2,%3};"
        : "+f"(d[0]), "+f"(d[1]), "+f"(d[2]), "+f"(d[3])
        : "r"(a[0]), "r"(a[1]), "r"(a[2]), "r"(a[3]), "r"(b[0]), "r"(b[1]));
}

__device__ __forceinline__ float block_sum1(float a, float* red) {
    #pragma unroll
    for (int off = 16; off > 0; off >>= 1) a += __shfl_xor_sync(0xffffffffu, a, off);
    int t = threadIdx.x;
    if ((t & 31) == 0) red[t >> 5] = a;
    __syncthreads();
    if (t == 0) {
        float s = 0.f;
        #pragma unroll
        for (int i = 0; i < 8; i++) s += red[i];
        red[8] = s;
    }
    __syncthreads();
    return red[8];
}

__device__ __forceinline__ void block_sum2(float& a, float& b, float* red) {
    #pragma unroll
    for (int off = 16; off > 0; off >>= 1) {
        a += __shfl_xor_sync(0xffffffffu, a, off);
        b += __shfl_xor_sync(0xffffffffu, b, off);
    }
    int t = threadIdx.x;
    if ((t & 31) == 0) { red[t >> 5] = a; red[8 + (t >> 5)] = b; }
    __syncthreads();
    if (t == 0) {
        float sa = 0.f, sb = 0.f;
        #pragma unroll
        for (int i = 0; i < 8; i++) { sa += red[i]; sb += red[8 + i]; }
        red[16] = sa; red[17] = sb;
    }
    __syncthreads();
    a = red[16]; b = red[17];
}

/* ---------------- embedding + LN (+ fp16 store) ---------------- */
__global__ __launch_bounds__(256) void embed_kernel(
    const int* __restrict__ ids, const float* __restrict__ we,
    const float* __restrict__ te, const float* __restrict__ pe,
    const float* __restrict__ lw, const float* __restrict__ lb,
    float* __restrict__ x, __half* __restrict__ xh)
{
    __shared__ float buf[HID];
    __shared__ float red[32];
    int row = blockIdx.x, t = threadIdx.x;
    int l = row & (LSEQ - 1);
    int id = ids[row];
    float s = 0.f;
    for (int j = t; j < HID; j += 256) {
        float v = we[(size_t)id * HID + j] + te[j] + pe[(size_t)l * HID + j];
        buf[j] = v; s += v;
    }
    float mean = block_sum1(s, red) * (1.f / HID);
    float vs = 0.f;
    for (int j = t; j < HID; j += 256) { float d = buf[j] - mean; vs += d * d; }
    float var = block_sum1(vs, red) * (1.f / HID);
    float inv = 1.0f / sqrtf(var + 1e-12f);
    for (int j = t; j < HID; j += 256) {
        float v = (buf[j] - mean) * inv * lw[j] + lb[j];
        x[(size_t)row * HID + j] = v;
        xh[(size_t)row * HID + j] = __float2half_rn(v);
    }
}

/* ---------------- residual + optional bias + LN (+ optional fp16 store) ---------------- */
__global__ __launch_bounds__(256) void ln_res_kernel(
    const float* __restrict__ resid, const float* __restrict__ y,
    const float* __restrict__ bias, const float* __restrict__ w,
    const float* __restrict__ bp, float* __restrict__ out,
    __half* __restrict__ oh)
{
    __shared__ float buf[HID];
    __shared__ float red[32];
    int row = blockIdx.x, t = threadIdx.x;
    float s = 0.f;
    for (int j = t; j < HID; j += 256) {
        float v = resid[(size_t)row * HID + j] + y[(size_t)row * HID + j];
        if (bias) v += bias[j];
        buf[j] = v; s += v;
    }
    float mean = block_sum1(s, red) * (1.f / HID);
    float vs = 0.f;
    for (int j = t; j < HID; j += 256) { float d = buf[j] - mean; vs += d * d; }
    float var = block_sum1(vs, red) * (1.f / HID);
    float inv = 1.0f / sqrtf(var + 1e-12f);
    for (int j = t; j < HID; j += 256) {
        float v = (buf[j] - mean) * inv * w[j] + bp[j];
        out[(size_t)row * HID + j] = v;
        if (oh) oh[(size_t)row * HID + j] = __float2half_rn(v);
    }
}

/* ---------------- weight transpose: W[NLAY,K,N] -> Th[NLAY(strided),N,K] fp16 ---------------- */
__global__ void tsplit_kernel(const float* __restrict__ W, __half* __restrict__ Th,
                              int K, int N, size_t tstride)
{
    __shared__ float tile[32][33];
    int layer = blockIdx.z;
    const float* Wp = W + (size_t)layer * K * N;
    __half* Tp = Th + (size_t)layer * tstride;
    int k0 = blockIdx.y * 32, n0 = blockIdx.x * 32;
    int tx = threadIdx.x, ty = threadIdx.y;
    #pragma unroll
    for (int j = 0; j < 4; j++)
        tile[ty + 8*j][tx] = Wp[(size_t)(k0 + ty + 8*j) * N + n0 + tx];
    __syncthreads();
    #pragma unroll
    for (int j = 0; j < 4; j++) {
        int n = n0 + ty + 8*j, k = k0 + tx;
        Tp[(size_t)n * K + k] = __float2half_rn(tile[tx][ty + 8*j]);
    }
}

/* ---------------- fp16 warp-MMA GEMM: C[M,N] = A[M,K] @ Bt[N,K]^T ----------------
   BK=64, 2-stage cp.async, ONE __syncthreads per K-slab.
   epi: 0 plain fp32 C; 1 silu + scatter to Cq/Ck/Cv (N=2304 packed QKV);
   2 gelu(v+bias) -> fp16 H. */
#define BK 64
#define LDS 72                     /* fp16 row stride in smem (144B: 4-bank rotation per row) */
#define ARR_ELEM (128*LDS)         /* 9216 halves per array */
#define STAGE_ELEM (2*ARR_ELEM)    /* 18432 halves per stage */
#define GEMM_SMEM (2*STAGE_ELEM*2) /* 73728 bytes */

__global__ __launch_bounds__(256) void gemm_f16(
    const __half* __restrict__ Ah, const __half* __restrict__ Bh,
    int K, int N, int epi, const float* __restrict__ bias,
    float* __restrict__ C, float* __restrict__ Cq, float* __restrict__ Ck, float* __restrict__ Cv,
    __half* __restrict__ H)
{
    extern __shared__ __half smem[];
    uint32_t smb = smem_u32(smem);
    int tid = threadIdx.x, lane = tid & 31, wid = tid >> 5;
    int bx = blockIdx.x, by = blockIdx.y;
    int wy = wid >> 2, wx = wid & 3;
    int m0 = wy * 64, n0 = wx * 32;

    const char* gsrc[2] = {
        (const char*)(Ah + (size_t)(by * 128) * K),
        (const char*)(Bh + (size_t)(bx * 128) * K)
    };

    int rb = tid >> 3, cq = tid & 7;   /* 32 row-groups x 8 col-chunks */

    float acc[4][4][4];
    #pragma unroll
    for (int mt = 0; mt < 4; mt++)
        #pragma unroll
        for (int nt = 0; nt < 4; nt++)
            #pragma unroll
            for (int e = 0; e < 4; e++) acc[mt][nt][e] = 0.f;

    int NKB = K / BK;

    /* prefetch slab 0 into stage 0 */
    {
        #pragma unroll
        for (int m = 0; m < 2; m++) {
            uint32_t sb = smb + (uint32_t)(m * ARR_ELEM) * 2;
            #pragma unroll
            for (int i = 0; i < 4; i++) {
                int r = i * 32 + rb;
                cp_async16(sb + (uint32_t)(r * LDS + cq * 8) * 2,
                           gsrc[m] + (size_t)r * K * 2 + cq * 16);
            }
        }
        cp_commit();
    }

    /* ldmatrix lane addressing */
    int aj = lane >> 3;
    int arow = ((aj & 1) << 3) + (lane & 7);
    int acol = (aj >> 1) << 3;
    int brow = ((aj >> 1) << 3) + (lane & 7);
    int bcol = (aj & 1) << 3;

    for (int kb = 0; kb < NKB; kb++) {
        cp_wait<0>();
        __syncthreads();

        /* prefetch next slab into the other stage (safe: all warps are past iter kb-1) */
        if (kb + 1 < NKB) {
            int s2 = (kb + 1) & 1;
            int koff = (kb + 1) * (BK * 2);
            #pragma unroll
            for (int m = 0; m < 2; m++) {
                uint32_t sb = smb + (uint32_t)(s2 * STAGE_ELEM + m * ARR_ELEM) * 2;
                #pragma unroll
                for (int i = 0; i < 4; i++) {
                    int r = i * 32 + rb;
                    cp_async16(sb + (uint32_t)(r * LDS + cq * 8) * 2,
                               gsrc[m] + (size_t)r * K * 2 + koff + cq * 16);
                }
            }
        }
        cp_commit();

        uint32_t stb = smb + (uint32_t)((kb & 1) * STAGE_ELEM) * 2;
        uint32_t aAh = stb;
        uint32_t aBh = stb + (uint32_t)ARR_ELEM * 2;

        #pragma unroll
        for (int ks = 0; ks < 4; ks++) {
            int kc = ks * 16;
            uint32_t ah[4][4];
            #pragma unroll
            for (int mt = 0; mt < 4; mt++) {
                uint32_t off = (uint32_t)((m0 + mt * 16 + arow) * LDS + kc + acol) * 2;
                ldsm_x4(ah[mt], aAh + off);
            }
            #pragma unroll
            for (int p = 0; p < 2; p++) {
                uint32_t boff = (uint32_t)((n0 + p * 16 + brow) * LDS + kc + bcol) * 2;
                uint32_t b4[4];
                ldsm_x4(b4, aBh + boff);
                #pragma unroll
                for (int sub = 0; sub < 2; sub++) {
                    int nt = p * 2 + sub;
                    #pragma unroll
                    for (int mt = 0; mt < 4; mt++)
                        mma16816(acc[mt][nt], ah[mt], b4 + sub * 2);
                }
            }
        }
    }

    int gm0 = by * 128 + m0;
    int gn0 = bx * 128 + n0;
    #pragma unroll
    for (int mt = 0; mt < 4; mt++) {
        #pragma unroll
        for (int nt = 0; nt < 4; nt++) {
            int row0 = gm0 + mt * 16 + (lane >> 2);
            int col0 = gn0 + nt * 8 + (lane & 3) * 2;
            if (epi == 2) {
                #pragma unroll
                for (int half = 0; half < 2; half++) {
                    int row = row0 + half * 8;
                    float v0 = acc[mt][nt][half * 2 + 0] + bias[col0];
                    float v1 = acc[mt][nt][half * 2 + 1] + bias[col0 + 1];
                    v0 = 0.5f * v0 * (1.0f + erff(v0 * 0.70710678118654752f));
                    v1 = 0.5f * v1 * (1.0f + erff(v1 * 0.70710678118654752f));
                    *(__half2*)(H + (size_t)row * N + col0) =
                        __half2(__float2half_rn(v0), __float2half_rn(v1));
                }
            } else {
                #pragma unroll
                for (int e = 0; e < 4; e++) {
                    int row = row0 + ((e >> 1) << 3);
                    int col = col0 + (e & 1);
                    float v = acc[mt][nt][e];
                    if (epi == 1) {
                        float sv = v / (1.0f + expf(-v));
                        int m = col / HID, cc = col - m * HID;
                        float* dst = (m == 0) ? Cq : (m == 1) ? Ck : Cv;
                        int b_ = row >> 9, l = row & (LSEQ - 1);
                        int h = cc >> 6, d = cc & 63;
                        dst[(size_t)((b_ * NH + h) * LSEQ + l) * DH + d] = sv;
                    } else {
                        C[(size_t)row * N + col] = v;
                    }
                }
            }
        }
    }
}

/* ---------------- gates: 4x [8192,768]@[768,12] + sigmoid -> [b,h,l] ---------------- */
__global__ __launch_bounds__(256) void gates_kernel(
    const float* __restrict__ x,
    const float* __restrict__ fdw, const float* __restrict__ sdw,
    const float* __restrict__ fgw, const float* __restrict__ sgw,
    const float* __restrict__ fdb, const float* __restrict__ sdb,
    float* __restrict__ fd, float* __restrict__ sd,
    float* __restrict__ fg, float* __restrict__ sg)
{
    __shared__ float xs[64][68];
    __shared__ float ws[64][48];
    int t = threadIdx.x;
    int blk = blockIdx.x;
    int r = t >> 2, g = t & 3;
    float acc[12];
    #pragma unroll
    for (int j = 0; j < 12; j++) acc[j] = 0.f;

    for (int kt = 0; kt < HID; kt += 64) {
        #pragma unroll
        for (int u = 0; u < 4; u++) {
            int idx = u * 256 + t;
            int xr = idx >> 4, xq = idx & 15;
            float4 xv = *(const float4*)(x + (size_t)(blk * 64 + xr) * HID + kt + xq * 4);
            xs[xr][xq * 4 + 0] = xv.x; xs[xr][xq * 4 + 1] = xv.y;
            xs[xr][xq * 4 + 2] = xv.z; xs[xr][xq * 4 + 3] = xv.w;
        }
        #pragma unroll
        for (int u = 0; u < 12; u++) {
            int idx = u * 256 + t;
            int wk = idx / 48, wj = idx % 48;
            int m = wj / 12, jj = wj % 12;
            const float* W = (m == 0) ? fdw : (m == 1) ? sdw : (m == 2) ? fgw : sgw;
            ws[wk][wj] = W[(size_t)(kt + wk) * NH + jj];
        }
        __syncthreads();
        for (int kk = 0; kk < 64; kk++) {
            float xv = xs[r][kk];
            #pragma unroll
            for (int j = 0; j < 12; j++) acc[j] += xv * ws[kk][g * 12 + j];
        }
        __syncthreads();
    }
    int token = blk * 64 + r;
    int b = token >> 9, l = token & (LSEQ - 1);
    float* dst = (g == 0) ? fd : (g == 1) ? sd : (g == 2) ? fg : sg;
    #pragma unroll
    for (int j = 0; j < 12; j++) {
        float vv = acc[j];
        if (g == 0) vv += fdb[j];
        else if (g == 1) vv += sdb[j];
        vv = 1.0f / (1.0f + expf(-vv));
        dst[(size_t)(b * NH + j) * LSEQ + l] = vv;
    }
}

__global__ __launch_bounds__(256) void cmean_kernel(
    const float* __restrict__ fd, const float* __restrict__ sd,
    float* __restrict__ fdm, float* __restrict__ sdm)
{
    __shared__ float red[32];
    int bid = blockIdx.x;
    int bh = bid >> 1, c = bid & 1;
    int t = threadIdx.x;
    float a = fd[(size_t)bh * LSEQ + c * 256 + t];
    float b = sd[(size_t)bh * LSEQ + c * 256 + t];
    block_sum2(a, b, red);
    if (t == 0) { fdm[bid] = a * (1.f / 256.f); sdm[bid] = b * (1.f / 256.f); }
}

#define SPAD 257
#define QPAD 66
#define DELTA_SMEM_BYTES ((4*4096 + 2*16896 + 40) * 4)

__global__ __launch_bounds__(256, 1) void delta_kernel(
    const float* __restrict__ q, const float* __restrict__ k, const float* __restrict__ v,
    const float* __restrict__ fg, const float* __restrict__ sg,
    const float* __restrict__ fdm, const float* __restrict__ sdm,
    float* __restrict__ o)
{
    extern __shared__ float smf[];
    float* Sf = smf;
    float* Ss = Sf + 4096;
    float* G  = Ss + 4096;
    float* A  = G + 4096;
    float* T0 = A + 4096;
    float* T1 = T0 + 16896;
    float* red = T1 + 16896;

    int t = threadIdx.x;
    int bh = blockIdx.x;
    int b = bh / NH, h = bh % NH;
    int d = t >> 2, g = t & 3, e0 = g * 16;

    #pragma unroll
    for (int j = 0; j < 16; j++) { Sf[d * 64 + e0 + j] = 0.f; Ss[d * 64 + e0 + j] = 0.f; }
    __syncthreads();

    const float* qb = q + (size_t)bh * LSEQ * DH;
    const float* kb = k + (size_t)bh * LSEQ * DH;
    const float* vb = v + (size_t)bh * LSEQ * DH;

    for (int c = 0; c < 2; c++) {
        int c0 = c * 256;
        float df = powf(fdm[bh * 2 + c], 256.0f);
        float ds = powf(sdm[bh * 2 + c], 256.0f);

        float pf = 0.f, ps = 0.f;
        #pragma unroll
        for (int j = 0; j < 16; j++) {
            int idx = d * 64 + e0 + j;
            float a = Sf[idx] * df; Sf[idx] = a; pf += a * a;
            float bb = Ss[idx] * ds; Ss[idx] = bb; ps += bb * bb;
        }
        block_sum2(pf, ps, red);
        float rf = 1.0f / (sqrtf(pf) + 1e-8f);
        float rs = 1.0f / (sqrtf(ps) + 1e-8f);

        #pragma unroll
        for (int u = 0; u < 16; u++) {
            int idx4 = u * 256 + t;
            int r = idx4 >> 4, e4 = (idx4 & 15) * 4;
            float4 kv = *(const float4*)(kb + (size_t)(c0 + r) * DH + e4);
            T0[(e4 + 0) * SPAD + r] = kv.x; T0[(e4 + 1) * SPAD + r] = kv.y;
            T0[(e4 + 2) * SPAD + r] = kv.z; T0[(e4 + 3) * SPAD + r] = kv.w;
            float4 vv = *(const float4*)(vb + (size_t)(c0 + r) * DH + e4);
            T1[(e4 + 0) * SPAD + r] = vv.x; T1[(e4 + 1) * SPAD + r] = vv.y;
            T1[(e4 + 2) * SPAD + r] = vv.z; T1[(e4 + 3) * SPAD + r] = vv.w;
        }
        __syncthreads();

        {
            float accG[16], accA[16];
            #pragma unroll
            for (int j = 0; j < 16; j++) { accG[j] = 0.f; accA[j] = 0.f; }
            for (int r = 0; r < 256; r++) {
                float kd = T0[d * SPAD + r];
                #pragma unroll
                for (int j = 0; j < 16; j++) {
                    accG[j] += kd * T0[(e0 + j) * SPAD + r];
                    accA[j] += kd * T1[(e0 + j) * SPAD + r];
                }
            }
            #pragma unroll
            for (int j = 0; j < 16; j++) { G[d * 64 + e0 + j] = accG[j]; A[d * 64 + e0 + j] = accA[j]; }
        }
        __syncthreads();

        #pragma unroll
        for (int u = 0; u < 16; u++) {
            int idx4 = u * 256 + t;
            int r = idx4 >> 4, e4 = (idx4 & 15) * 4;
            float4 qv = *(const float4*)(qb + (size_t)(c0 + r) * DH + e4);
            T0[r * QPAD + e4 + 0] = qv.x; T0[r * QPAD + e4 + 1] = qv.y;
            T0[r * QPAD + e4 + 2] = qv.z; T0[r * QPAD + e4 + 3] = qv.w;
        }
        __syncthreads();

        {
            float of[16], os[16];
            #pragma unroll
            for (int j = 0; j < 16; j++) { of[j] = 0.f; os[j] = 0.f; }
            for (int kk = 0; kk < 64; kk++) {
                float qv = T0[d * QPAD + kk];
                #pragma unroll
                for (int j = 0; j < 16; j++) {
                    of[j] += qv * Sf[kk * 64 + e0 + j];
                    os[j] += qv * Ss[kk * 64 + e0 + j];
                }
            }
            float fgv = fg[(size_t)bh * LSEQ + c0 + d];
            float sgv = sg[(size_t)bh * LSEQ + c0 + d];
            float* orow = o + (size_t)(b * LSEQ + c0 + d) * HID + h * DH + e0;
            #pragma unroll
            for (int j = 0; j < 16; j++)
                orow[j] = 0.6f * fgv * of[j] * rf + 0.4f * sgv * os[j] * rs;
        }

        {
            float tf[16], ts[16];
            #pragma unroll
            for (int j = 0; j < 16; j++) { tf[j] = 0.f; ts[j] = 0.f; }
            for (int kk = 0; kk < 64; kk++) {
                float gv = G[d * 64 + kk];
                #pragma unroll
                for (int j = 0; j < 16; j++) {
                    tf[j] += gv * Sf[kk * 64 + e0 + j];
                    ts[j] += gv * Ss[kk * 64 + e0 + j];
                }
            }
            __syncthreads();
            float nf = 0.f, ns = 0.f;
            #pragma unroll
            for (int j = 0; j < 16; j++) {
                int idx = d * 64 + e0 + j;
                float sv = Sf[idx] + A[idx] - tf[j] * rf;
                Sf[idx] = sv; nf += sv * sv;
                float sw = Ss[idx] + A[idx] - ts[j] * rs;
                Ss[idx] = sw; ns += sw * sw;
            }
            block_sum2(nf, ns, red);
            float qf = 1.0f / (sqrtf(nf) + 1e-8f);
            float qs = 1.0f / (sqrtf(ns) + 1e-8f);
            #pragma unroll
            for (int j = 0; j < 16; j++) {
                int idx = d * 64 + e0 + j;
                Sf[idx] *= qf; Ss[idx] *= qs;
            }
            __syncthreads();
        }
    }
}

/* ---------------- per-(b,l,h) rms norm over d=64 -> fp16 ---------------- */
__global__ __launch_bounds__(256) void rms_kernel(
    const float* __restrict__ o, const float* __restrict__ w,
    __half* __restrict__ oh)
{
    int warp = threadIdx.x >> 5, lane = threadIdx.x & 31;
    size_t row = (size_t)blockIdx.x * 8 + warp;
    const float2* p = (const float2*)(o + row * DH) + lane;
    float2 v = *p;
    float ss = v.x * v.x + v.y * v.y;
    #pragma unroll
    for (int off = 16; off > 0; off >>= 1) ss += __shfl_xor_sync(0xffffffffu, ss, off);
    float inv = 1.0f / sqrtf(ss * (1.f / 64.f) + 1e-6f);
    float v0 = v.x * inv * w[lane * 2];
    float v1 = v.y * inv * w[lane * 2 + 1];
    ((__half2*)(oh + row * DH))[lane] = __half2(__float2half_rn(v0), __float2half_rn(v1));
}

static float* symf(const void* sym) { void* p = nullptr; cudaGetSymbolAddress(&p, sym); return (float*)p; }
static __half* symh(const void* sym) { void* p = nullptr; cudaGetSymbolAddress(&p, sym); return (__half*)p; }

extern "C" void kernel_launch(void* const* d_in, const int* in_sizes, int n_in,
                              void* d_out, int out_size)
{
    const int*   ids = (const int*)  d_in[0];
    const float* we  = (const float*)d_in[1];
    const float* te  = (const float*)d_in[2];
    const float* pe  = (const float*)d_in[3];
    const float* elw = (const float*)d_in[4];
    const float* elb = (const float*)d_in[5];
    const float* qw  = (const float*)d_in[6];
    const float* kw  = (const float*)d_in[7];
    const float* vw  = (const float*)d_in[8];
    const float* fdw = (const float*)d_in[9];
    const float* fdb = (const float*)d_in[10];
    const float* sdw = (const float*)d_in[11];
    const float* sdb = (const float*)d_in[12];
    const float* fgw = (const float*)d_in[13];
    const float* sgw = (const float*)d_in[14];
    const float* onw = (const float*)d_in[15];
    const float* ow  = (const float*)d_in[16];
    const float* alw = (const float*)d_in[17];
    const float* alb = (const float*)d_in[18];
    const float* w1  = (const float*)d_in[19];
    const float* b1  = (const float*)d_in[20];
    const float* w2  = (const float*)d_in[21];
    const float* b2  = (const float*)d_in[22];
    const float* flw = (const float*)d_in[23];
    const float* flb = (const float*)d_in[24];
    float* out = (float*)d_out;

    float* px  = symf(g_x);  float* pq  = symf(g_q);  float* pk  = symf(g_k);
    float* pv  = symf(g_v);  float* po  = symf(g_o);  float* py  = symf(g_y);
    float* pfd = symf(g_fd); float* psd = symf(g_sd);
    float* pfg = symf(g_fg); float* psg = symf(g_sg);
    float* pfdm = symf(g_fdm); float* psdm = symf(g_sdm);
    __half* pwh = symh(g_wh);
    __half* pxh = symh(g_xh);
    __half* phh = pxh + (size_t)NTOK * HID;

    static bool attr_done = false;
    if (!attr_done) {
        cudaFuncSetAttribute(delta_kernel, cudaFuncAttributeMaxDynamicSharedMemorySize, DELTA_SMEM_BYTES);
        cudaFuncSetAttribute(gemm_f16, cudaFuncAttributeMaxDynamicSharedMemorySize, GEMM_SMEM);
        attr_done = true;
    }

    dim3 tb(32, 8);
    tsplit_kernel<<<dim3(HID/32, HID/32, NLAY), tb>>>(qw, pwh,            HID, HID, WLAYER);
    tsplit_kernel<<<dim3(HID/32, HID/32, NLAY), tb>>>(kw, pwh + WQKV,     HID, HID, WLAYER);
    tsplit_kernel<<<dim3(HID/32, HID/32, NLAY), tb>>>(vw, pwh + 2*WQKV,   HID, HID, WLAYER);
    tsplit_kernel<<<dim3(HID/32, HID/32, NLAY), tb>>>(ow, pwh + 3*WQKV,   HID, HID, WLAYER);
    tsplit_kernel<<<dim3(FFND/32, HID/32, NLAY), tb>>>(w1, pwh + 4*WQKV,        HID, FFND, WLAYER);
    tsplit_kernel<<<dim3(HID/32, FFND/32, NLAY), tb>>>(w2, pwh + 4*WQKV + WFFN, FFND, HID, WLAYER);

    embed_kernel<<<NTOK, 256>>>(ids, we, te, pe, elw, elb, px, pxh);

    dim3 gQKV(3*HID / 128, NTOK / 128);
    dim3 gO(HID / 128, NTOK / 128);
    dim3 gF1(FFND / 128, NTOK / 128);

    for (int i = 0; i < NLAY; i++) {
        size_t base = (size_t)i * WLAYER;

        gemm_f16<<<gQKV, 256, GEMM_SMEM>>>(pxh, pwh + base,
            HID, 3*HID, 1, nullptr, nullptr, pq, pk, pv, nullptr);

        gates_kernel<<<NTOK / 64, 256>>>(px,
            fdw + (size_t)i * HID * NH, sdw + (size_t)i * HID * NH,
            fgw + (size_t)i * HID * NH, sgw + (size_t)i * HID * NH,
            fdb + (size_t)i * NH, sdb + (size_t)i * NH,
            pfd, psd, pfg, psg);

        cmean_kernel<<<BATCH * NH * 2, 256>>>(pfd, psd, pfdm, psdm);
        delta_kernel<<<BATCH * NH, 256, DELTA_SMEM_BYTES>>>(pq, pk, pv, pfg, psg, pfdm, psdm, po);
        rms_kernel<<<(NTOK * NH) / 8, 256>>>(po, onw + (size_t)i * DH, pxh);

        gemm_f16<<<gO, 256, GEMM_SMEM>>>(pxh, pwh + base + 3*WQKV,
            HID, HID, 0, nullptr, py, nullptr, nullptr, nullptr, nullptr);

        ln_res_kernel<<<NTOK, 256>>>(px, py, nullptr,
            alw + (size_t)i * HID, alb + (size_t)i * HID, px, pxh);

        gemm_f16<<<gF1, 256, GEMM_SMEM>>>(pxh, pwh + base + 4*WQKV,
            HID, FFND, 2, b1 + (size_t)i * FFND, nullptr, nullptr, nullptr, nullptr, phh);

        gemm_f16<<<gO, 256, GEMM_SMEM>>>(phh, pwh + base + 4*WQKV + WFFN,
            FFND, HID, 0, nullptr, py, nullptr, nullptr, nullptr, nullptr);

        float* dst = (i == NLAY - 1) ? out : px;
        __half* doh = (i == NLAY - 1) ? nullptr : pxh;
        ln_res_kernel<<<NTOK, 256>>>(px, py, b2 + (size_t)i * HID,
            flw + (size_t)i * HID, flb + (size_t)i * HID, dst, doh);
    }
}